// round 1
// baseline (speedup 1.0000x reference)
#include <cuda_runtime.h>
#include <math.h>
#include <stdint.h>

// Problem constants (fixed by the benchmark)
#define BB 64
#define TT 20
#define KK 50
#define EE 100
#define HH 64
#define NROWS (5*BB*KK + 2*BB)   // 16128 gathered rows for Qf/prior
#define PITCH 101                // smem pitch for conflict-free E-dots

// ---------------- scratch (no allocations allowed) ----------------
__device__ float g_A[BB*KK*KK];     // A[b,k,j] = alpha[itemset[b,k]] . rho[itemset[b,j]]
__device__ float g_rda0[BB*TT*KK];  // rho[itemset[b,j]] . alpha[item_ids[b,t]]
__device__ float g_P[BB*TT*KK];     // rho[item_ids[b,t]] . alpha[itemset[b,k]]
__device__ float g_ra00[BB*TT];     // rho[item0] . alpha[item0]
__device__ float g_kesc[BB*KK];
__device__ float g_kes0[BB*TT];
__device__ double g_acc;

__global__ void init_kernel() { g_acc = 0.0; }

// ---------------- p_l - q_l over all 16128 gathered rows ----------------
// one warp per row; w1 transposed in smem -> conflict-free; fused prior sum
__global__ void rows_kernel(const float* __restrict__ alpha, const float* __restrict__ rho,
                            const float* __restrict__ lam,   const float* __restrict__ beta,
                            const float* __restrict__ mu_tab,const float* __restrict__ theta,
                            const float* __restrict__ gamma,
                            const float* __restrict__ w1, const float* __restrict__ b1,
                            const float* __restrict__ w2, const float* __restrict__ b2,
                            const float* __restrict__ sigma, const float* __restrict__ mu,
                            const int* __restrict__ itemset, const int* __restrict__ userid)
{
    __shared__ float w1t[EE*HH];     // [e][j]
    __shared__ float w2s[HH], b1s[HH];
    __shared__ float vbuf[4][EE];
    int tid = threadIdx.x;
    for (int i = tid; i < EE*HH; i += blockDim.x) {
        int e = i / HH, j = i % HH;
        w1t[i] = w1[j*EE + e];
    }
    if (tid < HH) { w2s[tid] = w2[tid]; b1s[tid] = b1[tid]; }
    __syncthreads();

    float b2v = b2[0];
    int lane = tid & 31, w = tid >> 5;
    int nwarps = gridDim.x * (blockDim.x >> 5);
    double local = 0.0;

    for (int r = blockIdx.x*(blockDim.x>>5) + w; r < NROWS; r += nwarps) {
        const float* tab; float sg, muv; int idx;
        if (r < 5*BB*KK) {
            int g = r / (BB*KK); int i = r - g*(BB*KK);
            idx = itemset[i];
            tab = (g==0)?alpha : (g==1)?rho : (g==2)?lam : (g==3)?beta : mu_tab;
            sg = sigma[g]; muv = mu[g];
        } else if (r < 5*BB*KK + BB) {
            idx = userid[r - 5*BB*KK]; tab = theta; sg = sigma[5]; muv = mu[5];
        } else {
            idx = userid[r - 5*BB*KK - BB]; tab = gamma; sg = sigma[6]; muv = mu[6];
        }
        const float* v = tab + (size_t)idx * EE;
        for (int e = lane; e < EE; e += 32) vbuf[w][e] = v[e];
        __syncwarp();

        float ss = 0.f;
        for (int e = lane; e < EE; e += 32) { float x = vbuf[w][e] - muv; ss = fmaf(x, x, ss); }

        float h0 = b1s[lane], h1 = b1s[lane+32];
        #pragma unroll 4
        for (int e = 0; e < EE; e++) {
            float ve = vbuf[w][e];
            h0 = fmaf(ve, w1t[e*HH + lane],      h0);
            h1 = fmaf(ve, w1t[e*HH + lane + 32], h1);
        }
        h0 = fmaxf(h0, 0.f); h1 = fmaxf(h1, 0.f);
        float z = h0*w2s[lane] + h1*w2s[lane+32];
        #pragma unroll
        for (int o = 16; o; o >>= 1) {
            z  += __shfl_xor_sync(0xffffffffu, z,  o);
            ss += __shfl_xor_sync(0xffffffffu, ss, o);
        }
        if (lane == 0) {
            float q = 1.f / (1.f + expf(-(z + b2v)));
            local += (double)((-0.5f/sg)*ss - q);
        }
        __syncwarp();
    }
    if (lane == 0) atomicAdd(&g_acc, local);
}

// ---------------- kesai values: one warp per output entry ----------------
__global__ void kes_kernel(const float* __restrict__ alpha, const float* __restrict__ lam,
                           const float* __restrict__ beta,  const float* __restrict__ theta,
                           const float* __restrict__ gamma, const float* __restrict__ prices,
                           const float* __restrict__ price_table,
                           const int* __restrict__ item_ids, const int* __restrict__ itemset,
                           const int* __restrict__ userid)
{
    int gw = (blockIdx.x*blockDim.x + threadIdx.x) >> 5;
    int lane = threadIdx.x & 31;
    const int NC = BB*KK, N0 = BB*TT;
    if (gw >= NC + N0) return;
    int idx, b, outi; float price;
    bool is_c = (gw < NC);
    if (is_c) { b = gw / KK; idx = itemset[gw];  price = price_table[idx]; outi = gw; }
    else      { int q = gw - NC; b = q / TT; idx = item_ids[q]; price = prices[q]; outi = q; }
    int u = userid[b];
    const float* a  = alpha + (size_t)idx*EE;
    const float* l  = lam   + (size_t)idx*EE;
    const float* be = beta  + (size_t)idx*EE;
    const float* th = theta + (size_t)u*EE;
    const float* ga = gamma + (size_t)u*EE;
    float s1=0.f, s2=0.f, s3=0.f;
    for (int e = lane; e < EE; e += 32) {
        s1 += l[e];
        s2 = fmaf(th[e], a[e], s2);
        s3 = fmaf(ga[e], be[e], s3);
    }
    #pragma unroll
    for (int o = 16; o; o >>= 1) {
        s1 += __shfl_xor_sync(0xffffffffu, s1, o);
        s2 += __shfl_xor_sync(0xffffffffu, s2, o);
        s3 += __shfl_xor_sync(0xffffffffu, s3, o);
    }
    if (lane == 0) {
        float val = (s1 + s2) * (1.f/EE) - (s3 * (1.f/EE)) * logf(price);
        if (is_c) g_kesc[outi] = val; else g_kes0[outi] = val;
    }
}

// ---------------- A[b,k,j] Gram matrix, one block per b ----------------
__global__ void a_kernel(const float* __restrict__ alpha, const float* __restrict__ rho,
                         const int* __restrict__ itemset)
{
    __shared__ float as[KK*PITCH], rs[KK*PITCH];
    int b = blockIdx.x, tid = threadIdx.x;
    for (int i = tid; i < KK*EE; i += blockDim.x) {
        int k = i/EE, e = i%EE; int row = itemset[b*KK + k];
        as[k*PITCH + e] = alpha[(size_t)row*EE + e];
        rs[k*PITCH + e] = rho  [(size_t)row*EE + e];
    }
    __syncthreads();
    for (int i = tid; i < KK*KK; i += blockDim.x) {
        int k = i/KK, j = i%KK;
        float s = 0.f;
        #pragma unroll 4
        for (int e = 0; e < EE; e++) s = fmaf(as[k*PITCH+e], rs[j*PITCH+e], s);
        g_A[(b*KK + k)*KK + j] = s;
    }
}

// ---------------- rda0[b,t,j] = rho_c[j] . alpha_item0[t] ----------------
__global__ void rda0_kernel(const float* __restrict__ alpha, const float* __restrict__ rho,
                            const int* __restrict__ itemset, const int* __restrict__ item_ids)
{
    __shared__ float rs[KK*PITCH], a0s[TT*PITCH];
    int b = blockIdx.x, tid = threadIdx.x;
    for (int i = tid; i < KK*EE; i += blockDim.x) {
        int k = i/EE, e = i%EE; int row = itemset[b*KK + k];
        rs[k*PITCH + e] = rho[(size_t)row*EE + e];
    }
    for (int i = tid; i < TT*EE; i += blockDim.x) {
        int t = i/EE, e = i%EE; int row = item_ids[b*TT + t];
        a0s[t*PITCH + e] = alpha[(size_t)row*EE + e];
    }
    __syncthreads();
    for (int i = tid; i < TT*KK; i += blockDim.x) {
        int t = i/KK, j = i%KK;
        float s = 0.f;
        #pragma unroll 4
        for (int e = 0; e < EE; e++) s = fmaf(a0s[t*PITCH+e], rs[j*PITCH+e], s);
        g_rda0[(b*TT + t)*KK + j] = s;
    }
}

// ---------------- P[b,t,k] = rho_item0[t] . alpha_c[k]; ra00 ----------------
__global__ void p_kernel(const float* __restrict__ alpha, const float* __restrict__ rho,
                         const int* __restrict__ itemset, const int* __restrict__ item_ids)
{
    __shared__ float as[KK*PITCH], r0s[TT*PITCH], a0s[TT*PITCH];
    int b = blockIdx.x, tid = threadIdx.x;
    for (int i = tid; i < KK*EE; i += blockDim.x) {
        int k = i/EE, e = i%EE; int row = itemset[b*KK + k];
        as[k*PITCH + e] = alpha[(size_t)row*EE + e];
    }
    for (int i = tid; i < TT*EE; i += blockDim.x) {
        int t = i/EE, e = i%EE; int row = item_ids[b*TT + t];
        r0s[t*PITCH + e] = rho  [(size_t)row*EE + e];
        a0s[t*PITCH + e] = alpha[(size_t)row*EE + e];
    }
    __syncthreads();
    for (int i = tid; i < TT*KK; i += blockDim.x) {
        int t = i/KK, k = i%KK;
        float s = 0.f;
        #pragma unroll 4
        for (int e = 0; e < EE; e++) s = fmaf(r0s[t*PITCH+e], as[k*PITCH+e], s);
        g_P[(b*TT + t)*KK + k] = s;
    }
    if (tid < TT) {
        float s = 0.f;
        #pragma unroll 4
        for (int e = 0; e < EE; e++) s = fmaf(r0s[tid*PITCH+e], a0s[tid*PITCH+e], s);
        g_ra00[b*TT + tid] = s;
    }
}

// ---------------- main basket kernel: one 64-thread CTA per (b,t) ----------------
// C[k,j] kept as a running register per thread j; look-ahead maxes via block reduce.
__global__ void basket_kernel(const int* __restrict__ item_ids, const int* __restrict__ itemset)
{
    __shared__ float sa[2], sb[2];
    int bt = blockIdx.x;
    int b = bt / TT;
    int tid = threadIdx.x;
    int item0 = item_ids[bt];

    bool mj = false; float kescj = 0.f, rda0j = 0.f, Cj = 0.f;
    if (tid < KK) {
        mj    = (itemset[b*KK + tid] != item0);
        kescj = g_kesc[b*KK + tid];
        rda0j = g_rda0[bt*KK + tid];
    }
    float ra00  = g_ra00[bt];
    float kes0v = g_kes0[bt];
    float cum = 0.f, Pcum = 0.f, acc = 0.f;

    for (int k = 0; k < KK; k++) {
        float akj = (tid < KK) ? g_A[(b*KK + k)*KK + tid] : 0.f;
        int ck = itemset[b*KK + k];                 // broadcast load
        float mf = (ck != item0) ? 1.f : 0.f;
        if (tid < KK) Cj = fmaf(mf, akj, Cj);
        cum += mf;
        float lenk  = 1.f + cum;
        float denom = (lenk + 1.f) * (float)EE;

        float c0 = -INFINITY, cc = -INFINITY;
        if (tid > k && tid < KK && mj) {
            float base = rda0j + Cj;
            c0 = (base + rda0j) / denom + kescj;    // val0
            cc = (base + akj)   / denom + kescj;    // valc
        }
        #pragma unroll
        for (int o = 16; o; o >>= 1) {
            c0 = fmaxf(c0, __shfl_xor_sync(0xffffffffu, c0, o));
            cc = fmaxf(cc, __shfl_xor_sync(0xffffffffu, cc, o));
        }
        int w = tid >> 5;
        if ((tid & 31) == 0) { sa[w] = c0; sb[w] = cc; }
        __syncthreads();
        float m0 = fmaxf(sa[0], sa[1]);
        float mc = fmaxf(sb[0], sb[1]);
        __syncthreads();

        Pcum = fmaf(mf, g_P[bt*KK + k], Pcum);      // broadcast load

        if (tid == k && mj) {
            float inv = 1.f / ((float)EE * lenk);
            float interact0 = (ra00  + Pcum) * inv;
            float interactc = (rda0j + Cj)   * inv;
            float Kes0 = kes0v + interact0 + fmaxf(0.f, m0);
            float KesC = kescj + interactc + fmaxf(0.f, mc);
            float x = Kes0 - KesC;
            acc += fminf(x, 0.f) - log1pf(expf(-fabsf(x)));   // stable log_sigmoid
        }
    }

    #pragma unroll
    for (int o = 16; o; o >>= 1) acc += __shfl_xor_sync(0xffffffffu, acc, o);
    if ((tid & 31) == 0) sa[tid >> 5] = acc;
    __syncthreads();
    if (tid == 0) atomicAdd(&g_acc, (double)(sa[0] + sa[1]));
}

__global__ void finish_kernel(float* out) { out[0] = (float)g_acc; }

// ---------------- launch ----------------
extern "C" void kernel_launch(void* const* d_in, const int* in_sizes, int n_in,
                              void* d_out, int out_size)
{
    const float* alpha       = (const float*)d_in[0];
    const float* rho         = (const float*)d_in[1];
    const float* lam         = (const float*)d_in[2];
    const float* beta        = (const float*)d_in[3];
    const float* mu_tab      = (const float*)d_in[4];
    const float* theta       = (const float*)d_in[5];
    const float* gamma       = (const float*)d_in[6];
    const float* w1          = (const float*)d_in[7];
    const float* b1          = (const float*)d_in[8];
    const float* w2          = (const float*)d_in[9];
    const float* b2          = (const float*)d_in[10];
    const float* sigma_list  = (const float*)d_in[11];
    const float* mu_list     = (const float*)d_in[12];
    const float* prices      = (const float*)d_in[13];
    const float* price_table = (const float*)d_in[14];
    const int*   item_ids    = (const int*)d_in[15];
    const int*   itemset     = (const int*)d_in[16];
    const int*   userid      = (const int*)d_in[17];
    // d_in[18] = batch_size (constant 64, unused)

    init_kernel<<<1, 1>>>();
    rows_kernel<<<128, 128>>>(alpha, rho, lam, beta, mu_tab, theta, gamma,
                              w1, b1, w2, b2, sigma_list, mu_list, itemset, userid);
    kes_kernel<<<560, 256>>>(alpha, lam, beta, theta, gamma, prices, price_table,
                             item_ids, itemset, userid);
    a_kernel<<<BB, 256>>>(alpha, rho, itemset);
    rda0_kernel<<<BB, 256>>>(alpha, rho, itemset, item_ids);
    p_kernel<<<BB, 256>>>(alpha, rho, itemset, item_ids);
    basket_kernel<<<BB*TT, 64>>>(item_ids, itemset);
    finish_kernel<<<1, 1>>>((float*)d_out);
}

// round 4
// speedup vs baseline: 2.4296x; 2.4296x over previous
#include <cuda_runtime.h>
#include <math.h>
#include <stdint.h>

// Problem constants (fixed by the benchmark)
#define BB 64
#define TT 20
#define KK 50
#define EE 100
#define HH 64
#define NROWS (5*BB*KK + 2*BB)    // 16128 gathered rows
#define RROWS 32                  // rows per block in rows role
#define NBLK_ROWS (NROWS/RROWS)   // 504
#define NBLK_BASK (BB*TT/8)       // 160

// role block ranges inside prep_kernel
#define ROLE_A_BASE    NBLK_ROWS          // 504
#define ROLE_RDA0_BASE (ROLE_A_BASE+BB)   // 568
#define ROLE_P_BASE    (ROLE_RDA0_BASE+BB)// 632
#define ROLE_KES_BASE  (ROLE_P_BASE+BB)   // 696
#define NBLK_PREP      (ROLE_KES_BASE+70) // 766

// ---------------- scratch (no allocations allowed) ----------------
__device__ float g_A[BB*KK*KK];     // A[b,k,j] = alpha_c[k] . rho_c[j]
__device__ float g_rda0[BB*TT*KK];  // rho_c[j] . alpha_item0[t]
__device__ float g_P[BB*TT*KK];     // rho_item0[t] . alpha_c[k]
__device__ float g_ra00[BB*TT];     // rho_item0 . alpha_item0
__device__ float g_kesc[BB*KK];
__device__ float g_kes0[BB*TT];
__device__ float g_part_rows[NBLK_ROWS];
__device__ float g_part_bask[NBLK_BASK];
__device__ unsigned g_count;        // zero-initialized at load; reset after each use

// =====================================================================
// prep_kernel: all independent pre-work fused, block-role dispatch.
// 256 threads/block, one 42KB shared buffer reused per role.
// =====================================================================
__global__ void __launch_bounds__(256) prep_kernel(
    const float* __restrict__ alpha, const float* __restrict__ rho,
    const float* __restrict__ lam,   const float* __restrict__ beta,
    const float* __restrict__ mu_tab,const float* __restrict__ theta,
    const float* __restrict__ gamma,
    const float* __restrict__ w1, const float* __restrict__ b1,
    const float* __restrict__ w2, const float* __restrict__ b2,
    const float* __restrict__ sigma, const float* __restrict__ mu,
    const float* __restrict__ prices, const float* __restrict__ price_table,
    const int* __restrict__ item_ids, const int* __restrict__ itemset,
    const int* __restrict__ userid)
{
    __shared__ __align__(16) char smem_raw[43008];
    int bx = blockIdx.x, tid = threadIdx.x;

    if (bx < NBLK_ROWS) {
        // ---------------- rows role: Qf + prior over 32 gathered rows ----------------
        float* w1t   = (float*)smem_raw;        // [e][h] pitch 68 -> 6800 floats
        float* v_rm  = w1t + EE*68;             // [row][e] 32*100
        float* ssrow = v_rm + RROWS*EE;         // 32
        float* w2s   = ssrow + RROWS;           // 64
        float* b1s   = w2s + HH;                // 64
        float* bsum  = b1s + HH;                // 1

        int base = bx * RROWS;
        int g; const float* tab; int uoff = 0;
        if (base < 5*BB*KK) {
            g = base / (BB*KK);
            tab = (g==0)?alpha : (g==1)?rho : (g==2)?lam : (g==3)?beta : mu_tab;
        } else if (base < 5*BB*KK + BB) { g = 5; tab = theta; uoff = base - 5*BB*KK; }
        else                            { g = 6; tab = gamma; uoff = base - 5*BB*KK - BB; }
        float sg = sigma[g], muv = mu[g];
        float b2v = b2[0];

        for (int i = tid; i < HH*EE; i += 256) {
            int h = i / EE, e = i - h*EE;
            w1t[e*68 + h] = w1[i];
        }
        if (tid < HH) { w2s[tid] = w2[tid]; b1s[tid] = b1[tid]; }
        if (tid == 0) *bsum = 0.f;

        for (int i = tid; i < RROWS*EE; i += 256) {
            int rl = i / EE, e = i - rl*EE;
            int idx;
            if (g < 5) idx = itemset[base - g*(BB*KK) + rl];
            else       idx = userid[uoff + rl];
            v_rm[rl*EE + e] = tab[(size_t)idx*EE + e];
        }
        __syncthreads();

        // prior sums, one thread per row
        if (tid < RROWS) {
            float ss = 0.f;
            for (int e = 0; e < EE; e++) { float x = v_rm[tid*EE + e] - muv; ss = fmaf(x, x, ss); }
            ssrow[tid] = ss;
        }

        // tiled GEMM: 2 rows x 4 hidden per thread (16 row-groups x 16 col-groups)
        int ty = tid >> 4, tx = tid & 15;
        float acc[2][4];
        #pragma unroll
        for (int i = 0; i < 2; i++)
            #pragma unroll
            for (int j = 0; j < 4; j++) acc[i][j] = b1s[tx*4 + j];

        for (int e = 0; e < EE; e++) {
            float4 wv = *(const float4*)&w1t[e*68 + tx*4];
            float vv0 = v_rm[(2*ty + 0)*EE + e];
            float vv1 = v_rm[(2*ty + 1)*EE + e];
            acc[0][0] = fmaf(vv0, wv.x, acc[0][0]);
            acc[0][1] = fmaf(vv0, wv.y, acc[0][1]);
            acc[0][2] = fmaf(vv0, wv.z, acc[0][2]);
            acc[0][3] = fmaf(vv0, wv.w, acc[0][3]);
            acc[1][0] = fmaf(vv1, wv.x, acc[1][0]);
            acc[1][1] = fmaf(vv1, wv.y, acc[1][1]);
            acc[1][2] = fmaf(vv1, wv.z, acc[1][2]);
            acc[1][3] = fmaf(vv1, wv.w, acc[1][3]);
        }

        float z[2];
        #pragma unroll
        for (int i = 0; i < 2; i++) {
            float s = 0.f;
            #pragma unroll
            for (int j = 0; j < 4; j++) s = fmaf(fmaxf(acc[i][j], 0.f), w2s[tx*4 + j], s);
            z[i] = s;
        }
        #pragma unroll
        for (int o = 8; o; o >>= 1) {
            z[0] += __shfl_xor_sync(0xffffffffu, z[0], o);
            z[1] += __shfl_xor_sync(0xffffffffu, z[1], o);
        }
        __syncthreads();
        if (tx == 0) {
            float local = 0.f;
            #pragma unroll
            for (int i = 0; i < 2; i++) {
                float q = 1.f / (1.f + expf(-(z[i] + b2v)));
                local += (-0.5f/sg)*ssrow[2*ty + i] - q;
            }
            atomicAdd(bsum, local);
        }
        __syncthreads();
        if (tid == 0) g_part_rows[bx] = *bsum;

    } else if (bx < ROLE_RDA0_BASE) {
        // ---------------- A[b,k,j] Gram, 4x4 tiles ----------------
        int b = bx - ROLE_A_BASE;
        float* sA = (float*)smem_raw;      // [e][k] pitch 52
        float* sR = sA + EE*52;
        for (int i = tid; i < 2*EE; i += 256) { int e = i >> 1, k = 50 + (i & 1); sA[e*52+k]=0.f; sR[e*52+k]=0.f; }
        for (int i = tid; i < KK*EE; i += 256) {
            int k = i / EE, e = i - k*EE; int row = itemset[b*KK + k];
            sA[e*52 + k] = alpha[(size_t)row*EE + e];
            sR[e*52 + k] = rho  [(size_t)row*EE + e];
        }
        __syncthreads();
        if (tid < 169) {
            int ty = tid / 13, tx = tid - ty*13;
            float acc[4][4] = {};
            for (int e = 0; e < EE; e++) {
                float4 av = *(const float4*)&sA[e*52 + ty*4];
                float4 rv = *(const float4*)&sR[e*52 + tx*4];
                float aa[4] = {av.x, av.y, av.z, av.w};
                float rr[4] = {rv.x, rv.y, rv.z, rv.w};
                #pragma unroll
                for (int i = 0; i < 4; i++)
                    #pragma unroll
                    for (int j = 0; j < 4; j++) acc[i][j] = fmaf(aa[i], rr[j], acc[i][j]);
            }
            #pragma unroll
            for (int i = 0; i < 4; i++) {
                int k = ty*4 + i; if (k >= KK) break;
                #pragma unroll
                for (int j = 0; j < 4; j++) {
                    int jj = tx*4 + j;
                    if (jj < KK) g_A[(b*KK + k)*KK + jj] = acc[i][j];
                }
            }
        }

    } else if (bx < ROLE_P_BASE) {
        // ---------------- rda0[b,t,j] = alpha_item0[t] . rho_c[j] ----------------
        int b = bx - ROLE_RDA0_BASE;
        float* sR  = (float*)smem_raw;     // [e][j] pitch 52
        float* sA0 = sR + EE*52;           // [e][t] pitch 20
        for (int i = tid; i < 2*EE; i += 256) { int e = i >> 1, k = 50 + (i & 1); sR[e*52+k]=0.f; }
        for (int i = tid; i < KK*EE; i += 256) {
            int k = i / EE, e = i - k*EE; int row = itemset[b*KK + k];
            sR[e*52 + k] = rho[(size_t)row*EE + e];
        }
        for (int i = tid; i < TT*EE; i += 256) {
            int t = i / EE, e = i - t*EE; int row = item_ids[b*TT + t];
            sA0[e*20 + t] = alpha[(size_t)row*EE + e];
        }
        __syncthreads();
        if (tid < 65) {
            int ty = tid / 13, tx = tid - ty*13;
            float acc[4][4] = {};
            for (int e = 0; e < EE; e++) {
                float4 av = *(const float4*)&sA0[e*20 + ty*4];
                float4 rv = *(const float4*)&sR[e*52 + tx*4];
                float aa[4] = {av.x, av.y, av.z, av.w};
                float rr[4] = {rv.x, rv.y, rv.z, rv.w};
                #pragma unroll
                for (int i = 0; i < 4; i++)
                    #pragma unroll
                    for (int j = 0; j < 4; j++) acc[i][j] = fmaf(aa[i], rr[j], acc[i][j]);
            }
            #pragma unroll
            for (int i = 0; i < 4; i++) {
                int t = ty*4 + i;
                #pragma unroll
                for (int j = 0; j < 4; j++) {
                    int jj = tx*4 + j;
                    if (jj < KK) g_rda0[(b*TT + t)*KK + jj] = acc[i][j];
                }
            }
        }

    } else if (bx < ROLE_KES_BASE) {
        // ---------------- P[b,t,k] = rho_item0[t] . alpha_c[k];  ra00 ----------------
        int b = bx - ROLE_P_BASE;
        float* sAC = (float*)smem_raw;     // [e][k] pitch 52
        float* sR0 = sAC + EE*52;          // [e][t] pitch 20
        float* sA0 = sR0 + EE*20;
        for (int i = tid; i < 2*EE; i += 256) { int e = i >> 1, k = 50 + (i & 1); sAC[e*52+k]=0.f; }
        for (int i = tid; i < KK*EE; i += 256) {
            int k = i / EE, e = i - k*EE; int row = itemset[b*KK + k];
            sAC[e*52 + k] = alpha[(size_t)row*EE + e];
        }
        for (int i = tid; i < TT*EE; i += 256) {
            int t = i / EE, e = i - t*EE; int row = item_ids[b*TT + t];
            sR0[e*20 + t] = rho  [(size_t)row*EE + e];
            sA0[e*20 + t] = alpha[(size_t)row*EE + e];
        }
        __syncthreads();
        if (tid < 65) {
            int ty = tid / 13, tx = tid - ty*13;
            float acc[4][4] = {};
            for (int e = 0; e < EE; e++) {
                float4 rv = *(const float4*)&sR0[e*20 + ty*4];
                float4 av = *(const float4*)&sAC[e*52 + tx*4];
                float rr[4] = {rv.x, rv.y, rv.z, rv.w};
                float aa[4] = {av.x, av.y, av.z, av.w};
                #pragma unroll
                for (int i = 0; i < 4; i++)
                    #pragma unroll
                    for (int j = 0; j < 4; j++) acc[i][j] = fmaf(rr[i], aa[j], acc[i][j]);
            }
            #pragma unroll
            for (int i = 0; i < 4; i++) {
                int t = ty*4 + i;
                #pragma unroll
                for (int j = 0; j < 4; j++) {
                    int kk = tx*4 + j;
                    if (kk < KK) g_P[(b*TT + t)*KK + kk] = acc[i][j];
                }
            }
        }
        if (tid >= 96 && tid < 96 + TT) {
            int t = tid - 96;
            float s = 0.f;
            for (int e = 0; e < EE; e++) s = fmaf(sR0[e*20 + t], sA0[e*20 + t], s);
            g_ra00[b*TT + t] = s;
        }

    } else {
        // ---------------- kes role: 8 warps x 8 entries per block ----------------
        int wi = tid >> 5, lane = tid & 31;
        const int NC = BB*KK, N0 = BB*TT;
        int gw_base = (bx - ROLE_KES_BASE)*64 + wi*8;
        #pragma unroll 1
        for (int q = 0; q < 8; q++) {
            int gw = gw_base + q;
            if (gw >= NC + N0) break;
            int idx, b, outi; float price;
            bool is_c = (gw < NC);
            if (is_c) { b = gw / KK; idx = itemset[gw];  price = price_table[idx]; outi = gw; }
            else      { int qq = gw - NC; b = qq / TT; idx = item_ids[qq]; price = prices[qq]; outi = qq; }
            int u = userid[b];
            const float* a  = alpha + (size_t)idx*EE;
            const float* l  = lam   + (size_t)idx*EE;
            const float* be = beta  + (size_t)idx*EE;
            const float* th = theta + (size_t)u*EE;
            const float* ga = gamma + (size_t)u*EE;
            float s1=0.f, s2=0.f, s3=0.f;
            for (int e = lane; e < EE; e += 32) {
                s1 += l[e];
                s2 = fmaf(th[e], a[e], s2);
                s3 = fmaf(ga[e], be[e], s3);
            }
            #pragma unroll
            for (int o = 16; o; o >>= 1) {
                s1 += __shfl_xor_sync(0xffffffffu, s1, o);
                s2 += __shfl_xor_sync(0xffffffffu, s2, o);
                s3 += __shfl_xor_sync(0xffffffffu, s3, o);
            }
            if (lane == 0) {
                float val = (s1 + s2) * (1.f/EE) - (s3 * (1.f/EE)) * logf(price);
                if (is_c) g_kesc[outi] = val; else g_kes0[outi] = val;
            }
        }
    }
}

// =====================================================================
// basket + fused final reduce: one warp per (b,t), barrier-free inner loop
// =====================================================================
__global__ void __launch_bounds__(256) basket_finish_kernel(
    const int* __restrict__ item_ids, const int* __restrict__ itemset, float* __restrict__ out)
{
    const unsigned FULL = 0xffffffffu;
    int w = threadIdx.x >> 5, lane = threadIdx.x & 31;
    int bt = blockIdx.x*8 + w;
    int b = bt / TT;
    int base = b*KK;
    int item0 = item_ids[bt];

    bool v1 = (lane < KK - 32);
    int c0i = itemset[base + lane];
    int c1i = v1 ? itemset[base + 32 + lane] : 0;
    bool mj0 = (c0i != item0);
    bool mj1 = v1 && (c1i != item0);
    unsigned ball0 = __ballot_sync(FULL, mj0);
    unsigned ball1 = __ballot_sync(FULL, mj1);
    int popA = __popc(ball0);

    float kesc0 = g_kesc[base + lane];
    float kesc1 = v1 ? g_kesc[base + 32 + lane] : 0.f;
    float rj0 = g_rda0[bt*KK + lane];
    float rj1 = v1 ? g_rda0[bt*KK + 32 + lane] : 0.f;
    float Pv0 = g_P[bt*KK + lane];
    float Pv1 = v1 ? g_P[bt*KK + 32 + lane] : 0.f;
    float ra00  = g_ra00[bt];
    float kes0v = g_kes0[bt];

    float Cj0 = 0.f, Cj1 = 0.f, Pcum = 0.f, acc = 0.f;

    for (int k = 0; k < KK; k++) {
        const float* arow = g_A + (size_t)(base + k)*KK;
        float ak0 = arow[lane];
        float ak1 = v1 ? arow[32 + lane] : 0.f;

        bool mk; int cnt;
        if (k < 32) { mk = (ball0 >> k) & 1u; cnt = __popc(ball0 & (0xffffffffu >> (31 - k))); }
        else        { mk = (ball1 >> (k-32)) & 1u; cnt = popA + __popc(ball1 & (0xffffffffu >> (63 - k))); }
        float mf = mk ? 1.f : 0.f;

        Cj0 = fmaf(mf, ak0, Cj0);
        Cj1 = fmaf(mf, ak1, Cj1);

        float lenk  = 1.f + (float)cnt;
        float rdenom = 1.f / ((lenk + 1.f) * (float)EE);

        float c0 = -INFINITY, cc = -INFINITY;
        if (mj0 && lane > k) {
            float bs = rj0 + Cj0;
            c0 = fmaf(bs + rj0, rdenom, kesc0);
            cc = fmaf(bs + ak0, rdenom, kesc0);
        }
        if (mj1 && (lane + 32) > k) {
            float bs = rj1 + Cj1;
            float x0 = fmaf(bs + rj1, rdenom, kesc1);
            float xc = fmaf(bs + ak1, rdenom, kesc1);
            c0 = fmaxf(c0, x0); cc = fmaxf(cc, xc);
        }
        #pragma unroll
        for (int o = 16; o; o >>= 1) {
            c0 = fmaxf(c0, __shfl_xor_sync(FULL, c0, o));
            cc = fmaxf(cc, __shfl_xor_sync(FULL, cc, o));
        }

        float Pk = __shfl_sync(FULL, (k < 32) ? Pv0 : Pv1, k & 31);
        Pcum = fmaf(mf, Pk, Pcum);

        if (lane == (k & 31)) {
            bool mjd = (k < 32) ? mj0 : mj1;
            if (mjd) {
                float kescd = (k < 32) ? kesc0 : kesc1;
                float rjd   = (k < 32) ? rj0   : rj1;
                float Cjd   = (k < 32) ? Cj0   : Cj1;
                float inv = 1.f / ((float)EE * lenk);
                float i0 = (ra00 + Pcum) * inv;
                float ic = (rjd + Cjd) * inv;
                float Kes0 = kes0v + i0 + fmaxf(0.f, c0);
                float KesC = kescd + ic + fmaxf(0.f, cc);
                float x = Kes0 - KesC;
                acc += fminf(x, 0.f) - log1pf(expf(-fabsf(x)));
            }
        }
    }

    #pragma unroll
    for (int o = 16; o; o >>= 1) acc += __shfl_xor_sync(FULL, acc, o);
    __shared__ float ws[8];
    __shared__ int is_last;
    if (lane == 0) ws[w] = acc;
    __syncthreads();
    if (threadIdx.x == 0) {
        float s = 0.f;
        #pragma unroll
        for (int i = 0; i < 8; i++) s += ws[i];
        g_part_bask[blockIdx.x] = s;
        __threadfence();
        unsigned t = atomicAdd(&g_count, 1u);
        is_last = (t == NBLK_BASK - 1) ? 1 : 0;
    }
    __syncthreads();

    if (is_last) {
        __threadfence();  // acquire: see all blocks' partial stores
        // final deterministic reduction by the last-arriving block
        int tid = threadIdx.x;
        double s = 0.0;
        for (int i = tid; i < NBLK_ROWS; i += 256) s += (double)g_part_rows[i];
        for (int i = tid; i < NBLK_BASK; i += 256) s += (double)g_part_bask[i];
        #pragma unroll
        for (int o = 16; o; o >>= 1) s += __shfl_xor_sync(FULL, s, o);
        __shared__ double wd[8];
        if ((tid & 31) == 0) wd[tid >> 5] = s;
        __syncthreads();
        if (tid == 0) {
            double t = 0.0;
            #pragma unroll
            for (int i = 0; i < 8; i++) t += wd[i];
            out[0] = (float)t;
            g_count = 0u;   // reset for the next graph replay (deterministic)
        }
    }
}

// ================= launch: 2 nodes, single stream, no driver objects ================
extern "C" void kernel_launch(void* const* d_in, const int* in_sizes, int n_in,
                              void* d_out, int out_size)
{
    const float* alpha       = (const float*)d_in[0];
    const float* rho         = (const float*)d_in[1];
    const float* lam         = (const float*)d_in[2];
    const float* beta        = (const float*)d_in[3];
    const float* mu_tab      = (const float*)d_in[4];
    const float* theta       = (const float*)d_in[5];
    const float* gamma       = (const float*)d_in[6];
    const float* w1          = (const float*)d_in[7];
    const float* b1          = (const float*)d_in[8];
    const float* w2          = (const float*)d_in[9];
    const float* b2          = (const float*)d_in[10];
    const float* sigma_list  = (const float*)d_in[11];
    const float* mu_list     = (const float*)d_in[12];
    const float* prices      = (const float*)d_in[13];
    const float* price_table = (const float*)d_in[14];
    const int*   item_ids    = (const int*)d_in[15];
    const int*   itemset     = (const int*)d_in[16];
    const int*   userid      = (const int*)d_in[17];

    prep_kernel<<<NBLK_PREP, 256>>>(alpha, rho, lam, beta, mu_tab, theta, gamma,
                                    w1, b1, w2, b2, sigma_list, mu_list,
                                    prices, price_table, item_ids, itemset, userid);
    basket_finish_kernel<<<NBLK_BASK, 256>>>(item_ids, itemset, (float*)d_out);
}

// round 5
// speedup vs baseline: 2.8645x; 1.1790x over previous
#include <cuda_runtime.h>
#include <math.h>
#include <stdint.h>

// Problem constants (fixed by the benchmark)
#define BB 64
#define TT 20
#define KK 50
#define EE 100
#define HH 64
#define NROWS (5*BB*KK + 2*BB)    // 16128 gathered rows
#define RROWS 32                  // rows per block in rows role
#define NBLK_ROWS (NROWS/RROWS)   // 504
#define NBLK_BASK (BB*5)          // 320: block = (b, t-quad of 4 warps)

// role block ranges inside prep_kernel
#define ROLE_A_BASE    NBLK_ROWS          // 504
#define ROLE_RDA0_BASE (ROLE_A_BASE+BB)   // 568
#define ROLE_P_BASE    (ROLE_RDA0_BASE+BB)// 632
#define ROLE_KES_BASE  (ROLE_P_BASE+BB)   // 696
#define NBLK_PREP      (ROLE_KES_BASE+70) // 766

// ---------------- scratch (no allocations allowed) ----------------
__device__ float g_A[BB*KK*KK];     // A[b,k,j] = alpha_c[k] . rho_c[j]
__device__ float g_rda0[BB*TT*KK];  // rho_c[j] . alpha_item0[t]
__device__ float g_P[BB*TT*KK];     // rho_item0[t] . alpha_c[k]
__device__ float g_ra00[BB*TT];     // rho_item0 . alpha_item0
__device__ float g_kesc[BB*KK];
__device__ float g_kes0[BB*TT];
__device__ float g_part_rows[NBLK_ROWS];
__device__ float g_part_bask[NBLK_BASK];
__device__ unsigned g_count;        // zero at load; reset after each use

// =====================================================================
// prep_kernel: all independent pre-work fused, block-role dispatch.
// (unchanged from R4 — validated)
// =====================================================================
__global__ void __launch_bounds__(256) prep_kernel(
    const float* __restrict__ alpha, const float* __restrict__ rho,
    const float* __restrict__ lam,   const float* __restrict__ beta,
    const float* __restrict__ mu_tab,const float* __restrict__ theta,
    const float* __restrict__ gamma,
    const float* __restrict__ w1, const float* __restrict__ b1,
    const float* __restrict__ w2, const float* __restrict__ b2,
    const float* __restrict__ sigma, const float* __restrict__ mu,
    const float* __restrict__ prices, const float* __restrict__ price_table,
    const int* __restrict__ item_ids, const int* __restrict__ itemset,
    const int* __restrict__ userid)
{
    __shared__ __align__(16) char smem_raw[43008];
    int bx = blockIdx.x, tid = threadIdx.x;

    if (bx < NBLK_ROWS) {
        // ---------------- rows role: Qf + prior over 32 gathered rows ----------------
        float* w1t   = (float*)smem_raw;        // [e][h] pitch 68
        float* v_rm  = w1t + EE*68;             // [row][e]
        float* ssrow = v_rm + RROWS*EE;
        float* w2s   = ssrow + RROWS;
        float* b1s   = w2s + HH;
        float* bsum  = b1s + HH;

        int base = bx * RROWS;
        int g; const float* tab; int uoff = 0;
        if (base < 5*BB*KK) {
            g = base / (BB*KK);
            tab = (g==0)?alpha : (g==1)?rho : (g==2)?lam : (g==3)?beta : mu_tab;
        } else if (base < 5*BB*KK + BB) { g = 5; tab = theta; uoff = base - 5*BB*KK; }
        else                            { g = 6; tab = gamma; uoff = base - 5*BB*KK - BB; }
        float sg = sigma[g], muv = mu[g];
        float b2v = b2[0];

        for (int i = tid; i < HH*EE; i += 256) {
            int h = i / EE, e = i - h*EE;
            w1t[e*68 + h] = w1[i];
        }
        if (tid < HH) { w2s[tid] = w2[tid]; b1s[tid] = b1[tid]; }
        if (tid == 0) *bsum = 0.f;

        for (int i = tid; i < RROWS*EE; i += 256) {
            int rl = i / EE, e = i - rl*EE;
            int idx;
            if (g < 5) idx = itemset[base - g*(BB*KK) + rl];
            else       idx = userid[uoff + rl];
            v_rm[rl*EE + e] = tab[(size_t)idx*EE + e];
        }
        __syncthreads();

        if (tid < RROWS) {
            float ss = 0.f;
            for (int e = 0; e < EE; e++) { float x = v_rm[tid*EE + e] - muv; ss = fmaf(x, x, ss); }
            ssrow[tid] = ss;
        }

        int ty = tid >> 4, tx = tid & 15;
        float acc[2][4];
        #pragma unroll
        for (int i = 0; i < 2; i++)
            #pragma unroll
            for (int j = 0; j < 4; j++) acc[i][j] = b1s[tx*4 + j];

        for (int e = 0; e < EE; e++) {
            float4 wv = *(const float4*)&w1t[e*68 + tx*4];
            float vv0 = v_rm[(2*ty + 0)*EE + e];
            float vv1 = v_rm[(2*ty + 1)*EE + e];
            acc[0][0] = fmaf(vv0, wv.x, acc[0][0]);
            acc[0][1] = fmaf(vv0, wv.y, acc[0][1]);
            acc[0][2] = fmaf(vv0, wv.z, acc[0][2]);
            acc[0][3] = fmaf(vv0, wv.w, acc[0][3]);
            acc[1][0] = fmaf(vv1, wv.x, acc[1][0]);
            acc[1][1] = fmaf(vv1, wv.y, acc[1][1]);
            acc[1][2] = fmaf(vv1, wv.z, acc[1][2]);
            acc[1][3] = fmaf(vv1, wv.w, acc[1][3]);
        }

        float z[2];
        #pragma unroll
        for (int i = 0; i < 2; i++) {
            float s = 0.f;
            #pragma unroll
            for (int j = 0; j < 4; j++) s = fmaf(fmaxf(acc[i][j], 0.f), w2s[tx*4 + j], s);
            z[i] = s;
        }
        #pragma unroll
        for (int o = 8; o; o >>= 1) {
            z[0] += __shfl_xor_sync(0xffffffffu, z[0], o);
            z[1] += __shfl_xor_sync(0xffffffffu, z[1], o);
        }
        __syncthreads();
        if (tx == 0) {
            float local = 0.f;
            #pragma unroll
            for (int i = 0; i < 2; i++) {
                float q = 1.f / (1.f + expf(-(z[i] + b2v)));
                local += (-0.5f/sg)*ssrow[2*ty + i] - q;
            }
            atomicAdd(bsum, local);
        }
        __syncthreads();
        if (tid == 0) g_part_rows[bx] = *bsum;

    } else if (bx < ROLE_RDA0_BASE) {
        // ---------------- A[b,k,j] Gram, 4x4 tiles ----------------
        int b = bx - ROLE_A_BASE;
        float* sA = (float*)smem_raw;      // [e][k] pitch 52
        float* sR = sA + EE*52;
        for (int i = tid; i < 2*EE; i += 256) { int e = i >> 1, k = 50 + (i & 1); sA[e*52+k]=0.f; sR[e*52+k]=0.f; }
        for (int i = tid; i < KK*EE; i += 256) {
            int k = i / EE, e = i - k*EE; int row = itemset[b*KK + k];
            sA[e*52 + k] = alpha[(size_t)row*EE + e];
            sR[e*52 + k] = rho  [(size_t)row*EE + e];
        }
        __syncthreads();
        if (tid < 169) {
            int ty = tid / 13, tx = tid - ty*13;
            float acc[4][4] = {};
            for (int e = 0; e < EE; e++) {
                float4 av = *(const float4*)&sA[e*52 + ty*4];
                float4 rv = *(const float4*)&sR[e*52 + tx*4];
                float aa[4] = {av.x, av.y, av.z, av.w};
                float rr[4] = {rv.x, rv.y, rv.z, rv.w};
                #pragma unroll
                for (int i = 0; i < 4; i++)
                    #pragma unroll
                    for (int j = 0; j < 4; j++) acc[i][j] = fmaf(aa[i], rr[j], acc[i][j]);
            }
            #pragma unroll
            for (int i = 0; i < 4; i++) {
                int k = ty*4 + i; if (k >= KK) break;
                #pragma unroll
                for (int j = 0; j < 4; j++) {
                    int jj = tx*4 + j;
                    if (jj < KK) g_A[(b*KK + k)*KK + jj] = acc[i][j];
                }
            }
        }

    } else if (bx < ROLE_P_BASE) {
        // ---------------- rda0[b,t,j] = alpha_item0[t] . rho_c[j] ----------------
        int b = bx - ROLE_RDA0_BASE;
        float* sR  = (float*)smem_raw;     // [e][j] pitch 52
        float* sA0 = sR + EE*52;           // [e][t] pitch 20
        for (int i = tid; i < 2*EE; i += 256) { int e = i >> 1, k = 50 + (i & 1); sR[e*52+k]=0.f; }
        for (int i = tid; i < KK*EE; i += 256) {
            int k = i / EE, e = i - k*EE; int row = itemset[b*KK + k];
            sR[e*52 + k] = rho[(size_t)row*EE + e];
        }
        for (int i = tid; i < TT*EE; i += 256) {
            int t = i / EE, e = i - t*EE; int row = item_ids[b*TT + t];
            sA0[e*20 + t] = alpha[(size_t)row*EE + e];
        }
        __syncthreads();
        if (tid < 65) {
            int ty = tid / 13, tx = tid - ty*13;
            float acc[4][4] = {};
            for (int e = 0; e < EE; e++) {
                float4 av = *(const float4*)&sA0[e*20 + ty*4];
                float4 rv = *(const float4*)&sR[e*52 + tx*4];
                float aa[4] = {av.x, av.y, av.z, av.w};
                float rr[4] = {rv.x, rv.y, rv.z, rv.w};
                #pragma unroll
                for (int i = 0; i < 4; i++)
                    #pragma unroll
                    for (int j = 0; j < 4; j++) acc[i][j] = fmaf(aa[i], rr[j], acc[i][j]);
            }
            #pragma unroll
            for (int i = 0; i < 4; i++) {
                int t = ty*4 + i;
                #pragma unroll
                for (int j = 0; j < 4; j++) {
                    int jj = tx*4 + j;
                    if (jj < KK) g_rda0[(b*TT + t)*KK + jj] = acc[i][j];
                }
            }
        }

    } else if (bx < ROLE_KES_BASE) {
        // ---------------- P[b,t,k] = rho_item0[t] . alpha_c[k];  ra00 ----------------
        int b = bx - ROLE_P_BASE;
        float* sAC = (float*)smem_raw;     // [e][k] pitch 52
        float* sR0 = sAC + EE*52;          // [e][t] pitch 20
        float* sA0 = sR0 + EE*20;
        for (int i = tid; i < 2*EE; i += 256) { int e = i >> 1, k = 50 + (i & 1); sAC[e*52+k]=0.f; }
        for (int i = tid; i < KK*EE; i += 256) {
            int k = i / EE, e = i - k*EE; int row = itemset[b*KK + k];
            sAC[e*52 + k] = alpha[(size_t)row*EE + e];
        }
        for (int i = tid; i < TT*EE; i += 256) {
            int t = i / EE, e = i - t*EE; int row = item_ids[b*TT + t];
            sR0[e*20 + t] = rho  [(size_t)row*EE + e];
            sA0[e*20 + t] = alpha[(size_t)row*EE + e];
        }
        __syncthreads();
        if (tid < 65) {
            int ty = tid / 13, tx = tid - ty*13;
            float acc[4][4] = {};
            for (int e = 0; e < EE; e++) {
                float4 rv = *(const float4*)&sR0[e*20 + ty*4];
                float4 av = *(const float4*)&sAC[e*52 + tx*4];
                float rr[4] = {rv.x, rv.y, rv.z, rv.w};
                float aa[4] = {av.x, av.y, av.z, av.w};
                #pragma unroll
                for (int i = 0; i < 4; i++)
                    #pragma unroll
                    for (int j = 0; j < 4; j++) acc[i][j] = fmaf(rr[i], aa[j], acc[i][j]);
            }
            #pragma unroll
            for (int i = 0; i < 4; i++) {
                int t = ty*4 + i;
                #pragma unroll
                for (int j = 0; j < 4; j++) {
                    int kk = tx*4 + j;
                    if (kk < KK) g_P[(b*TT + t)*KK + kk] = acc[i][j];
                }
            }
        }
        if (tid >= 96 && tid < 96 + TT) {
            int t = tid - 96;
            float s = 0.f;
            for (int e = 0; e < EE; e++) s = fmaf(sR0[e*20 + t], sA0[e*20 + t], s);
            g_ra00[b*TT + t] = s;
        }

    } else {
        // ---------------- kes role: 8 warps x 8 entries per block ----------------
        int wi = tid >> 5, lane = tid & 31;
        const int NC = BB*KK, N0 = BB*TT;
        int gw_base = (bx - ROLE_KES_BASE)*64 + wi*8;
        #pragma unroll 1
        for (int q = 0; q < 8; q++) {
            int gw = gw_base + q;
            if (gw >= NC + N0) break;
            int idx, b, outi; float price;
            bool is_c = (gw < NC);
            if (is_c) { b = gw / KK; idx = itemset[gw];  price = price_table[idx]; outi = gw; }
            else      { int qq = gw - NC; b = qq / TT; idx = item_ids[qq]; price = prices[qq]; outi = qq; }
            int u = userid[b];
            const float* a  = alpha + (size_t)idx*EE;
            const float* l  = lam   + (size_t)idx*EE;
            const float* be = beta  + (size_t)idx*EE;
            const float* th = theta + (size_t)u*EE;
            const float* ga = gamma + (size_t)u*EE;
            float s1=0.f, s2=0.f, s3=0.f;
            for (int e = lane; e < EE; e += 32) {
                s1 += l[e];
                s2 = fmaf(th[e], a[e], s2);
                s3 = fmaf(ga[e], be[e], s3);
            }
            #pragma unroll
            for (int o = 16; o; o >>= 1) {
                s1 += __shfl_xor_sync(0xffffffffu, s1, o);
                s2 += __shfl_xor_sync(0xffffffffu, s2, o);
                s3 += __shfl_xor_sync(0xffffffffu, s3, o);
            }
            if (lane == 0) {
                float val = (s1 + s2) * (1.f/EE) - (s3 * (1.f/EE)) * logf(price);
                if (is_c) g_kesc[outi] = val; else g_kes0[outi] = val;
            }
        }
    }
}

// order-preserving float<->int map (self-inverse)
__device__ __forceinline__ int f_ord(float f) {
    int i = __float_as_int(f);
    return i ^ ((i >> 31) & 0x7FFFFFFF);
}
__device__ __forceinline__ float ord_f(int i) {
    i ^= ((i >> 31) & 0x7FFFFFFF);
    return __int_as_float(i);
}

// =====================================================================
// basket + fused final reduce
// block = (b, t-quad): 4 warps, one warp per (b,t). A[b] staged in smem.
// Per-k maxes via native REDUX.MAX; P prefix hoisted to a one-time scan.
// =====================================================================
__global__ void __launch_bounds__(128) basket_finish_kernel(
    const int* __restrict__ item_ids, const int* __restrict__ itemset, float* __restrict__ out)
{
    __shared__ float sA[KK*KK];     // 10KB: A[b] row-major [k][j]
    __shared__ float ws[4];
    __shared__ int is_last;
    const unsigned FULL = 0xffffffffu;

    int w = threadIdx.x >> 5, lane = threadIdx.x & 31;
    int b  = blockIdx.x / 5;
    int t  = (blockIdx.x % 5)*4 + w;
    int bt = b*TT + t;
    int base = b*KK;

    for (int i = threadIdx.x; i < KK*KK; i += 128) sA[i] = g_A[base*KK + i];

    int item0 = item_ids[bt];
    bool v1 = (lane < KK - 32);
    int c0i = itemset[base + lane];
    int c1i = v1 ? itemset[base + 32 + lane] : 0;
    bool mj0 = (c0i != item0);
    bool mj1 = v1 && (c1i != item0);
    unsigned ball0 = __ballot_sync(FULL, mj0);
    unsigned ball1 = __ballot_sync(FULL, mj1);
    int popA = __popc(ball0);

    float kesc0 = g_kesc[base + lane];
    float kesc1 = v1 ? g_kesc[base + 32 + lane] : 0.f;
    float rj0 = g_rda0[bt*KK + lane];
    float rj1 = v1 ? g_rda0[bt*KK + 32 + lane] : 0.f;
    float ra00  = g_ra00[bt];
    float kes0v = g_kes0[bt];

    // one-time masked inclusive prefix scan of P over k (two 32-halves)
    float px0 = mj0 ? g_P[bt*KK + lane] : 0.f;
    float px1 = mj1 ? g_P[bt*KK + 32 + lane] : 0.f;
    #pragma unroll
    for (int d = 1; d < 32; d <<= 1) {
        float v = __shfl_up_sync(FULL, px0, d);
        if (lane >= d) px0 += v;
    }
    float tot0 = __shfl_sync(FULL, px0, 31);
    #pragma unroll
    for (int d = 1; d < 32; d <<= 1) {
        float v = __shfl_up_sync(FULL, px1, d);
        if (lane >= d) px1 += v;
    }
    px1 += tot0;   // px0 = Pcum at k=lane; px1 = Pcum at k=lane+32

    __syncthreads();   // sA ready

    float Cj0 = 0.f, Cj1 = 0.f, acc = 0.f;

    #pragma unroll 2
    for (int k = 0; k < KK; k++) {
        float ak0 = sA[k*KK + lane];
        float ak1 = v1 ? sA[k*KK + 32 + lane] : 0.f;

        bool mk; int cnt;
        if (k < 32) { mk = (ball0 >> k) & 1u; cnt = __popc(ball0 & (0xffffffffu >> (31 - k))); }
        else        { mk = (ball1 >> (k-32)) & 1u; cnt = popA + __popc(ball1 & (0xffffffffu >> (63 - k))); }
        float mf = mk ? 1.f : 0.f;

        Cj0 = fmaf(mf, ak0, Cj0);
        Cj1 = fmaf(mf, ak1, Cj1);

        float lenk   = 1.f + (float)cnt;
        float rdenom = __fdividef(1.f, (lenk + 1.f) * (float)EE);

        float c0 = -INFINITY, cc = -INFINITY;
        if (mj0 && lane > k) {
            float bs = rj0 + Cj0;
            c0 = fmaf(bs + rj0, rdenom, kesc0);
            cc = fmaf(bs + ak0, rdenom, kesc0);
        }
        if (mj1 && (lane + 32) > k) {
            float bs = rj1 + Cj1;
            float y0 = fmaf(bs + rj1, rdenom, kesc1);
            float yc = fmaf(bs + ak1, rdenom, kesc1);
            c0 = fmaxf(c0, y0); cc = fmaxf(cc, yc);
        }

        // warp max via native REDUX on order-preserving ints
        int m0i = __reduce_max_sync(FULL, f_ord(c0));
        int mci = __reduce_max_sync(FULL, f_ord(cc));

        if (lane == (k & 31)) {
            bool mjd = (k < 32) ? mj0 : mj1;
            if (mjd) {
                float m0 = ord_f(m0i);
                float mc = ord_f(mci);
                float kescd = (k < 32) ? kesc0 : kesc1;
                float rjd   = (k < 32) ? rj0   : rj1;
                float Cjd   = (k < 32) ? Cj0   : Cj1;
                float Pcd   = (k < 32) ? px0   : px1;
                float inv = __fdividef(1.f, (float)EE * lenk);
                float i0v = (ra00 + Pcd) * inv;
                float icv = (rjd  + Cjd) * inv;
                float Kes0 = kes0v + i0v + fmaxf(0.f, m0);
                float KesC = kescd + icv + fmaxf(0.f, mc);
                float xq = Kes0 - KesC;
                acc += fminf(xq, 0.f) - log1pf(expf(-fabsf(xq)));
            }
        }
    }

    #pragma unroll
    for (int o = 16; o; o >>= 1) acc += __shfl_xor_sync(FULL, acc, o);
    if (lane == 0) ws[w] = acc;
    __syncthreads();
    if (threadIdx.x == 0) {
        float s = ws[0] + ws[1] + ws[2] + ws[3];
        g_part_bask[blockIdx.x] = s;
        __threadfence();
        unsigned tk = atomicAdd(&g_count, 1u);
        is_last = (tk == NBLK_BASK - 1) ? 1 : 0;
    }
    __syncthreads();

    if (is_last) {
        __threadfence();  // acquire: see all blocks' partial stores
        int tid = threadIdx.x;
        double s = 0.0;
        for (int i = tid; i < NBLK_ROWS; i += 128) s += (double)g_part_rows[i];
        for (int i = tid; i < NBLK_BASK; i += 128) s += (double)g_part_bask[i];
        #pragma unroll
        for (int o = 16; o; o >>= 1) s += __shfl_xor_sync(FULL, s, o);
        __shared__ double wd[4];
        if (lane == 0) wd[tid >> 5] = s;
        __syncthreads();
        if (tid == 0) {
            double tt = wd[0] + wd[1] + wd[2] + wd[3];
            out[0] = (float)tt;
            g_count = 0u;   // reset for next replay
        }
    }
}

// ================= launch: 2 nodes, single stream, no driver objects ================
extern "C" void kernel_launch(void* const* d_in, const int* in_sizes, int n_in,
                              void* d_out, int out_size)
{
    const float* alpha       = (const float*)d_in[0];
    const float* rho         = (const float*)d_in[1];
    const float* lam         = (const float*)d_in[2];
    const float* beta        = (const float*)d_in[3];
    const float* mu_tab      = (const float*)d_in[4];
    const float* theta       = (const float*)d_in[5];
    const float* gamma       = (const float*)d_in[6];
    const float* w1          = (const float*)d_in[7];
    const float* b1          = (const float*)d_in[8];
    const float* w2          = (const float*)d_in[9];
    const float* b2          = (const float*)d_in[10];
    const float* sigma_list  = (const float*)d_in[11];
    const float* mu_list     = (const float*)d_in[12];
    const float* prices      = (const float*)d_in[13];
    const float* price_table = (const float*)d_in[14];
    const int*   item_ids    = (const int*)d_in[15];
    const int*   itemset     = (const int*)d_in[16];
    const int*   userid      = (const int*)d_in[17];

    prep_kernel<<<NBLK_PREP, 256>>>(alpha, rho, lam, beta, mu_tab, theta, gamma,
                                    w1, b1, w2, b2, sigma_list, mu_list,
                                    prices, price_table, item_ids, itemset, userid);
    basket_finish_kernel<<<NBLK_BASK, 128>>>(item_ids, itemset, (float*)d_out);
}

// round 6
// speedup vs baseline: 3.1340x; 1.0941x over previous
#include <cuda_runtime.h>
#include <math.h>
#include <stdint.h>

// Problem constants (fixed by the benchmark)
#define BB 64
#define TT 20
#define KK 50
#define EE 100
#define HH 64
#define NROWS (5*BB*KK + 2*BB)    // 16128 gathered rows
#define RROWS 32                  // rows per block in rows role
#define NBLK_ROWS (NROWS/RROWS)   // 504
#define NBLK_BASK (BB*5)          // 320 blocks: (b, t-quad); 4 warps per (b,t)

// role block ranges inside prep_kernel
#define ROLE_A_BASE    NBLK_ROWS          // 504
#define ROLE_RDA0_BASE (ROLE_A_BASE+BB)   // 568
#define ROLE_P_BASE    (ROLE_RDA0_BASE+BB)// 632
#define ROLE_KES_BASE  (ROLE_P_BASE+BB)   // 696
#define NBLK_PREP      (ROLE_KES_BASE+70) // 766

// ---------------- scratch (no allocations allowed) ----------------
__device__ float g_A[BB*KK*KK];     // A[b,k,j] = alpha_c[k] . rho_c[j]
__device__ float g_rda0[BB*TT*KK];  // rho_c[j] . alpha_item0[t]
__device__ float g_P[BB*TT*KK];     // rho_item0[t] . alpha_c[k]
__device__ float g_ra00[BB*TT];     // rho_item0 . alpha_item0
__device__ float g_kesc[BB*KK];
__device__ float g_kes0[BB*TT];
__device__ float g_part_rows[NBLK_ROWS];
__device__ float g_part_bask[NBLK_BASK];
__device__ unsigned g_count;        // zero at load; reset after each use

// =====================================================================
// prep_kernel: all independent pre-work fused, block-role dispatch.
// (unchanged — validated)
// =====================================================================
__global__ void __launch_bounds__(256) prep_kernel(
    const float* __restrict__ alpha, const float* __restrict__ rho,
    const float* __restrict__ lam,   const float* __restrict__ beta,
    const float* __restrict__ mu_tab,const float* __restrict__ theta,
    const float* __restrict__ gamma,
    const float* __restrict__ w1, const float* __restrict__ b1,
    const float* __restrict__ w2, const float* __restrict__ b2,
    const float* __restrict__ sigma, const float* __restrict__ mu,
    const float* __restrict__ prices, const float* __restrict__ price_table,
    const int* __restrict__ item_ids, const int* __restrict__ itemset,
    const int* __restrict__ userid)
{
    __shared__ __align__(16) char smem_raw[43008];
    int bx = blockIdx.x, tid = threadIdx.x;

    if (bx < NBLK_ROWS) {
        // ---------------- rows role: Qf + prior over 32 gathered rows ----------------
        float* w1t   = (float*)smem_raw;        // [e][h] pitch 68
        float* v_rm  = w1t + EE*68;             // [row][e]
        float* ssrow = v_rm + RROWS*EE;
        float* w2s   = ssrow + RROWS;
        float* b1s   = w2s + HH;
        float* bsum  = b1s + HH;

        int base = bx * RROWS;
        int g; const float* tab; int uoff = 0;
        if (base < 5*BB*KK) {
            g = base / (BB*KK);
            tab = (g==0)?alpha : (g==1)?rho : (g==2)?lam : (g==3)?beta : mu_tab;
        } else if (base < 5*BB*KK + BB) { g = 5; tab = theta; uoff = base - 5*BB*KK; }
        else                            { g = 6; tab = gamma; uoff = base - 5*BB*KK - BB; }
        float sg = sigma[g], muv = mu[g];
        float b2v = b2[0];

        for (int i = tid; i < HH*EE; i += 256) {
            int h = i / EE, e = i - h*EE;
            w1t[e*68 + h] = w1[i];
        }
        if (tid < HH) { w2s[tid] = w2[tid]; b1s[tid] = b1[tid]; }
        if (tid == 0) *bsum = 0.f;

        for (int i = tid; i < RROWS*EE; i += 256) {
            int rl = i / EE, e = i - rl*EE;
            int idx;
            if (g < 5) idx = itemset[base - g*(BB*KK) + rl];
            else       idx = userid[uoff + rl];
            v_rm[rl*EE + e] = tab[(size_t)idx*EE + e];
        }
        __syncthreads();

        if (tid < RROWS) {
            float ss = 0.f;
            for (int e = 0; e < EE; e++) { float x = v_rm[tid*EE + e] - muv; ss = fmaf(x, x, ss); }
            ssrow[tid] = ss;
        }

        int ty = tid >> 4, tx = tid & 15;
        float acc[2][4];
        #pragma unroll
        for (int i = 0; i < 2; i++)
            #pragma unroll
            for (int j = 0; j < 4; j++) acc[i][j] = b1s[tx*4 + j];

        for (int e = 0; e < EE; e++) {
            float4 wv = *(const float4*)&w1t[e*68 + tx*4];
            float vv0 = v_rm[(2*ty + 0)*EE + e];
            float vv1 = v_rm[(2*ty + 1)*EE + e];
            acc[0][0] = fmaf(vv0, wv.x, acc[0][0]);
            acc[0][1] = fmaf(vv0, wv.y, acc[0][1]);
            acc[0][2] = fmaf(vv0, wv.z, acc[0][2]);
            acc[0][3] = fmaf(vv0, wv.w, acc[0][3]);
            acc[1][0] = fmaf(vv1, wv.x, acc[1][0]);
            acc[1][1] = fmaf(vv1, wv.y, acc[1][1]);
            acc[1][2] = fmaf(vv1, wv.z, acc[1][2]);
            acc[1][3] = fmaf(vv1, wv.w, acc[1][3]);
        }

        float z[2];
        #pragma unroll
        for (int i = 0; i < 2; i++) {
            float s = 0.f;
            #pragma unroll
            for (int j = 0; j < 4; j++) s = fmaf(fmaxf(acc[i][j], 0.f), w2s[tx*4 + j], s);
            z[i] = s;
        }
        #pragma unroll
        for (int o = 8; o; o >>= 1) {
            z[0] += __shfl_xor_sync(0xffffffffu, z[0], o);
            z[1] += __shfl_xor_sync(0xffffffffu, z[1], o);
        }
        __syncthreads();
        if (tx == 0) {
            float local = 0.f;
            #pragma unroll
            for (int i = 0; i < 2; i++) {
                float q = 1.f / (1.f + expf(-(z[i] + b2v)));
                local += (-0.5f/sg)*ssrow[2*ty + i] - q;
            }
            atomicAdd(bsum, local);
        }
        __syncthreads();
        if (tid == 0) g_part_rows[bx] = *bsum;

    } else if (bx < ROLE_RDA0_BASE) {
        // ---------------- A[b,k,j] Gram, 4x4 tiles ----------------
        int b = bx - ROLE_A_BASE;
        float* sA = (float*)smem_raw;      // [e][k] pitch 52
        float* sR = sA + EE*52;
        for (int i = tid; i < 2*EE; i += 256) { int e = i >> 1, k = 50 + (i & 1); sA[e*52+k]=0.f; sR[e*52+k]=0.f; }
        for (int i = tid; i < KK*EE; i += 256) {
            int k = i / EE, e = i - k*EE; int row = itemset[b*KK + k];
            sA[e*52 + k] = alpha[(size_t)row*EE + e];
            sR[e*52 + k] = rho  [(size_t)row*EE + e];
        }
        __syncthreads();
        if (tid < 169) {
            int ty = tid / 13, tx = tid - ty*13;
            float acc[4][4] = {};
            for (int e = 0; e < EE; e++) {
                float4 av = *(const float4*)&sA[e*52 + ty*4];
                float4 rv = *(const float4*)&sR[e*52 + tx*4];
                float aa[4] = {av.x, av.y, av.z, av.w};
                float rr[4] = {rv.x, rv.y, rv.z, rv.w};
                #pragma unroll
                for (int i = 0; i < 4; i++)
                    #pragma unroll
                    for (int j = 0; j < 4; j++) acc[i][j] = fmaf(aa[i], rr[j], acc[i][j]);
            }
            #pragma unroll
            for (int i = 0; i < 4; i++) {
                int k = ty*4 + i; if (k >= KK) break;
                #pragma unroll
                for (int j = 0; j < 4; j++) {
                    int jj = tx*4 + j;
                    if (jj < KK) g_A[(b*KK + k)*KK + jj] = acc[i][j];
                }
            }
        }

    } else if (bx < ROLE_P_BASE) {
        // ---------------- rda0[b,t,j] = alpha_item0[t] . rho_c[j] ----------------
        int b = bx - ROLE_RDA0_BASE;
        float* sR  = (float*)smem_raw;     // [e][j] pitch 52
        float* sA0 = sR + EE*52;           // [e][t] pitch 20
        for (int i = tid; i < 2*EE; i += 256) { int e = i >> 1, k = 50 + (i & 1); sR[e*52+k]=0.f; }
        for (int i = tid; i < KK*EE; i += 256) {
            int k = i / EE, e = i - k*EE; int row = itemset[b*KK + k];
            sR[e*52 + k] = rho[(size_t)row*EE + e];
        }
        for (int i = tid; i < TT*EE; i += 256) {
            int t = i / EE, e = i - t*EE; int row = item_ids[b*TT + t];
            sA0[e*20 + t] = alpha[(size_t)row*EE + e];
        }
        __syncthreads();
        if (tid < 65) {
            int ty = tid / 13, tx = tid - ty*13;
            float acc[4][4] = {};
            for (int e = 0; e < EE; e++) {
                float4 av = *(const float4*)&sA0[e*20 + ty*4];
                float4 rv = *(const float4*)&sR[e*52 + tx*4];
                float aa[4] = {av.x, av.y, av.z, av.w};
                float rr[4] = {rv.x, rv.y, rv.z, rv.w};
                #pragma unroll
                for (int i = 0; i < 4; i++)
                    #pragma unroll
                    for (int j = 0; j < 4; j++) acc[i][j] = fmaf(aa[i], rr[j], acc[i][j]);
            }
            #pragma unroll
            for (int i = 0; i < 4; i++) {
                int t = ty*4 + i;
                #pragma unroll
                for (int j = 0; j < 4; j++) {
                    int jj = tx*4 + j;
                    if (jj < KK) g_rda0[(b*TT + t)*KK + jj] = acc[i][j];
                }
            }
        }

    } else if (bx < ROLE_KES_BASE) {
        // ---------------- P[b,t,k] = rho_item0[t] . alpha_c[k];  ra00 ----------------
        int b = bx - ROLE_P_BASE;
        float* sAC = (float*)smem_raw;     // [e][k] pitch 52
        float* sR0 = sAC + EE*52;          // [e][t] pitch 20
        float* sA0 = sR0 + EE*20;
        for (int i = tid; i < 2*EE; i += 256) { int e = i >> 1, k = 50 + (i & 1); sAC[e*52+k]=0.f; }
        for (int i = tid; i < KK*EE; i += 256) {
            int k = i / EE, e = i - k*EE; int row = itemset[b*KK + k];
            sAC[e*52 + k] = alpha[(size_t)row*EE + e];
        }
        for (int i = tid; i < TT*EE; i += 256) {
            int t = i / EE, e = i - t*EE; int row = item_ids[b*TT + t];
            sR0[e*20 + t] = rho  [(size_t)row*EE + e];
            sA0[e*20 + t] = alpha[(size_t)row*EE + e];
        }
        __syncthreads();
        if (tid < 65) {
            int ty = tid / 13, tx = tid - ty*13;
            float acc[4][4] = {};
            for (int e = 0; e < EE; e++) {
                float4 rv = *(const float4*)&sR0[e*20 + ty*4];
                float4 av = *(const float4*)&sAC[e*52 + tx*4];
                float rr[4] = {rv.x, rv.y, rv.z, rv.w};
                float aa[4] = {av.x, av.y, av.z, av.w};
                #pragma unroll
                for (int i = 0; i < 4; i++)
                    #pragma unroll
                    for (int j = 0; j < 4; j++) acc[i][j] = fmaf(rr[i], aa[j], acc[i][j]);
            }
            #pragma unroll
            for (int i = 0; i < 4; i++) {
                int t = ty*4 + i;
                #pragma unroll
                for (int j = 0; j < 4; j++) {
                    int kk = tx*4 + j;
                    if (kk < KK) g_P[(b*TT + t)*KK + kk] = acc[i][j];
                }
            }
        }
        if (tid >= 96 && tid < 96 + TT) {
            int t = tid - 96;
            float s = 0.f;
            for (int e = 0; e < EE; e++) s = fmaf(sR0[e*20 + t], sA0[e*20 + t], s);
            g_ra00[b*TT + t] = s;
        }

    } else {
        // ---------------- kes role: 8 warps x 8 entries per block ----------------
        int wi = tid >> 5, lane = tid & 31;
        const int NC = BB*KK, N0 = BB*TT;
        int gw_base = (bx - ROLE_KES_BASE)*64 + wi*8;
        #pragma unroll 1
        for (int q = 0; q < 8; q++) {
            int gw = gw_base + q;
            if (gw >= NC + N0) break;
            int idx, b, outi; float price;
            bool is_c = (gw < NC);
            if (is_c) { b = gw / KK; idx = itemset[gw];  price = price_table[idx]; outi = gw; }
            else      { int qq = gw - NC; b = qq / TT; idx = item_ids[qq]; price = prices[qq]; outi = qq; }
            int u = userid[b];
            const float* a  = alpha + (size_t)idx*EE;
            const float* l  = lam   + (size_t)idx*EE;
            const float* be = beta  + (size_t)idx*EE;
            const float* th = theta + (size_t)u*EE;
            const float* ga = gamma + (size_t)u*EE;
            float s1=0.f, s2=0.f, s3=0.f;
            for (int e = lane; e < EE; e += 32) {
                s1 += l[e];
                s2 = fmaf(th[e], a[e], s2);
                s3 = fmaf(ga[e], be[e], s3);
            }
            #pragma unroll
            for (int o = 16; o; o >>= 1) {
                s1 += __shfl_xor_sync(0xffffffffu, s1, o);
                s2 += __shfl_xor_sync(0xffffffffu, s2, o);
                s3 += __shfl_xor_sync(0xffffffffu, s3, o);
            }
            if (lane == 0) {
                float val = (s1 + s2) * (1.f/EE) - (s3 * (1.f/EE)) * logf(price);
                if (is_c) g_kesc[outi] = val; else g_kes0[outi] = val;
            }
        }
    }
}

// order-preserving float<->int map (self-inverse)
__device__ __forceinline__ int f_ord(float f) {
    int i = __float_as_int(f);
    return i ^ ((i >> 31) & 0x7FFFFFFF);
}
__device__ __forceinline__ float ord_f(int i) {
    i ^= ((i >> 31) & 0x7FFFFFFF);
    return __int_as_float(i);
}

// =====================================================================
// basket + fused final reduce
// block = (b, t-quad): 512 threads = 16 warps; 4 warps per (b,t), each
// owning a k-chunk. A[b] staged in smem. Chunk base Cj computed with
// cheap pipelined masked FMAs; only ~13 REDUX-bearing iterations/warp.
// =====================================================================
__global__ void __launch_bounds__(512) basket_finish_kernel(
    const int* __restrict__ item_ids, const int* __restrict__ itemset, float* __restrict__ out)
{
    __shared__ float sA[KK*KK];     // 10KB: A[b] row-major [k][j]
    __shared__ float ws[16];
    __shared__ int is_last;
    const unsigned FULL = 0xffffffffu;

    int w = threadIdx.x >> 5, lane = threadIdx.x & 31;
    int bt_local = w >> 2;          // 0..3  (which t in the quad)
    int chunk    = w & 3;           // 0..3  (which k-chunk)
    int b  = blockIdx.x / 5;
    int t  = (blockIdx.x % 5)*4 + bt_local;
    int bt = b*TT + t;
    int base = b*KK;

    // chunk boundaries over k: [0,12),[12,25),[25,37),[37,50)
    int kstart = (chunk*KK) >> 2;
    int kend   = ((chunk+1)*KK) >> 2;

    for (int i = threadIdx.x; i < KK*KK; i += 512) sA[i] = g_A[base*KK + i];

    int item0 = item_ids[bt];
    bool v1 = (lane < KK - 32);
    int c0i = itemset[base + lane];
    int c1i = v1 ? itemset[base + 32 + lane] : 0;
    bool mj0 = (c0i != item0);
    bool mj1 = v1 && (c1i != item0);
    unsigned ball0 = __ballot_sync(FULL, mj0);
    unsigned ball1 = __ballot_sync(FULL, mj1);
    int popA = __popc(ball0);

    float kesc0 = g_kesc[base + lane];
    float kesc1 = v1 ? g_kesc[base + 32 + lane] : 0.f;
    float rj0 = g_rda0[bt*KK + lane];
    float rj1 = v1 ? g_rda0[bt*KK + 32 + lane] : 0.f;
    float ra00  = g_ra00[bt];
    float kes0v = g_kes0[bt];

    // one-time masked inclusive prefix scan of P over k (two 32-halves)
    float px0 = mj0 ? g_P[bt*KK + lane] : 0.f;
    float px1 = mj1 ? g_P[bt*KK + 32 + lane] : 0.f;
    #pragma unroll
    for (int d = 1; d < 32; d <<= 1) {
        float v = __shfl_up_sync(FULL, px0, d);
        if (lane >= d) px0 += v;
    }
    float tot0 = __shfl_sync(FULL, px0, 31);
    #pragma unroll
    for (int d = 1; d < 32; d <<= 1) {
        float v = __shfl_up_sync(FULL, px1, d);
        if (lane >= d) px1 += v;
    }
    px1 += tot0;   // px0 = Pcum at k=lane; px1 = Pcum at k=lane+32

    __syncthreads();   // sA ready

    // chunk base: Cj up to kstart (cheap masked FMAs, pipelined smem loads)
    float Cj0 = 0.f, Cj1 = 0.f, acc = 0.f;
    for (int k = 0; k < kstart; k++) {
        float mf = ((k < 32 ? (ball0 >> k) : (ball1 >> (k-32))) & 1u) ? 1.f : 0.f;
        Cj0 = fmaf(mf, sA[k*KK + lane], Cj0);
        if (v1) Cj1 = fmaf(mf, sA[k*KK + 32 + lane], Cj1);
    }

    for (int k = kstart; k < kend; k++) {
        float ak0 = sA[k*KK + lane];
        float ak1 = v1 ? sA[k*KK + 32 + lane] : 0.f;

        bool mk; int cnt;
        if (k < 32) { mk = (ball0 >> k) & 1u; cnt = __popc(ball0 & (0xffffffffu >> (31 - k))); }
        else        { mk = (ball1 >> (k-32)) & 1u; cnt = popA + __popc(ball1 & (0xffffffffu >> (63 - k))); }
        float mf = mk ? 1.f : 0.f;

        Cj0 = fmaf(mf, ak0, Cj0);
        Cj1 = fmaf(mf, ak1, Cj1);

        float lenk   = 1.f + (float)cnt;
        float rdenom = __fdividef(1.f, (lenk + 1.f) * (float)EE);

        float c0 = -INFINITY, cc = -INFINITY;
        if (mj0 && lane > k) {
            float bs = rj0 + Cj0;
            c0 = fmaf(bs + rj0, rdenom, kesc0);
            cc = fmaf(bs + ak0, rdenom, kesc0);
        }
        if (mj1 && (lane + 32) > k) {
            float bs = rj1 + Cj1;
            float y0 = fmaf(bs + rj1, rdenom, kesc1);
            float yc = fmaf(bs + ak1, rdenom, kesc1);
            c0 = fmaxf(c0, y0); cc = fmaxf(cc, yc);
        }

        // warp max via native REDUX on order-preserving ints
        int m0i = __reduce_max_sync(FULL, f_ord(c0));
        int mci = __reduce_max_sync(FULL, f_ord(cc));

        if (lane == (k & 31)) {
            bool mjd = (k < 32) ? mj0 : mj1;
            if (mjd) {
                float m0 = ord_f(m0i);
                float mc = ord_f(mci);
                float kescd = (k < 32) ? kesc0 : kesc1;
                float rjd   = (k < 32) ? rj0   : rj1;
                float Cjd   = (k < 32) ? Cj0   : Cj1;
                float Pcd   = (k < 32) ? px0   : px1;
                float inv = __fdividef(1.f, (float)EE * lenk);
                float i0v = (ra00 + Pcd) * inv;
                float icv = (rjd  + Cjd) * inv;
                float Kes0 = kes0v + i0v + fmaxf(0.f, m0);
                float KesC = kescd + icv + fmaxf(0.f, mc);
                float xq = Kes0 - KesC;
                acc += fminf(xq, 0.f) - log1pf(expf(-fabsf(xq)));
            }
        }
    }

    #pragma unroll
    for (int o = 16; o; o >>= 1) acc += __shfl_xor_sync(FULL, acc, o);
    if (lane == 0) ws[w] = acc;
    __syncthreads();
    if (threadIdx.x == 0) {
        float s = 0.f;
        #pragma unroll
        for (int i = 0; i < 16; i++) s += ws[i];
        g_part_bask[blockIdx.x] = s;
        __threadfence();
        unsigned tk = atomicAdd(&g_count, 1u);
        is_last = (tk == NBLK_BASK - 1) ? 1 : 0;
    }
    __syncthreads();

    if (is_last) {
        __threadfence();  // acquire: see all blocks' partial stores
        int tid = threadIdx.x;
        double s = 0.0;
        for (int i = tid; i < NBLK_ROWS; i += 512) s += (double)g_part_rows[i];
        for (int i = tid; i < NBLK_BASK; i += 512) s += (double)g_part_bask[i];
        #pragma unroll
        for (int o = 16; o; o >>= 1) s += __shfl_xor_sync(FULL, s, o);
        __shared__ double wd[16];
        if (lane == 0) wd[tid >> 5] = s;
        __syncthreads();
        if (tid == 0) {
            double tt = 0.0;
            #pragma unroll
            for (int i = 0; i < 16; i++) tt += wd[i];
            out[0] = (float)tt;
            g_count = 0u;   // reset for next replay
        }
    }
}

// ================= launch: 2 nodes, single stream, no driver objects ================
extern "C" void kernel_launch(void* const* d_in, const int* in_sizes, int n_in,
                              void* d_out, int out_size)
{
    const float* alpha       = (const float*)d_in[0];
    const float* rho         = (const float*)d_in[1];
    const float* lam         = (const float*)d_in[2];
    const float* beta        = (const float*)d_in[3];
    const float* mu_tab      = (const float*)d_in[4];
    const float* theta       = (const float*)d_in[5];
    const float* gamma       = (const float*)d_in[6];
    const float* w1          = (const float*)d_in[7];
    const float* b1          = (const float*)d_in[8];
    const float* w2          = (const float*)d_in[9];
    const float* b2          = (const float*)d_in[10];
    const float* sigma_list  = (const float*)d_in[11];
    const float* mu_list     = (const float*)d_in[12];
    const float* prices      = (const float*)d_in[13];
    const float* price_table = (const float*)d_in[14];
    const int*   item_ids    = (const int*)d_in[15];
    const int*   itemset     = (const int*)d_in[16];
    const int*   userid      = (const int*)d_in[17];

    prep_kernel<<<NBLK_PREP, 256>>>(alpha, rho, lam, beta, mu_tab, theta, gamma,
                                    w1, b1, w2, b2, sigma_list, mu_list,
                                    prices, price_table, item_ids, itemset, userid);
    basket_finish_kernel<<<NBLK_BASK, 512>>>(item_ids, itemset, (float*)d_out);
}

// round 7
// speedup vs baseline: 3.4521x; 1.1015x over previous
#include <cuda_runtime.h>
#include <math.h>
#include <stdint.h>

// Problem constants (fixed by the benchmark)
#define BB 64
#define TT 20
#define KK 50
#define EE 100
#define HH 64
#define NROWS (5*BB*KK + 2*BB)    // 16128 gathered rows
#define RROWS 32                  // rows per block in rows role
#define NBLK_ROWS (NROWS/RROWS)   // 504

// block-role layout (single fused kernel)
#define ROLE_A_BASE    NBLK_ROWS           // 504: 64 blocks, A Gram per b
#define ROLE_RDA0_BASE (ROLE_A_BASE+BB)    // 568: 64 blocks
#define ROLE_P_BASE    (ROLE_RDA0_BASE+BB) // 632: 64 blocks
#define ROLE_KES_BASE  (ROLE_P_BASE+BB)    // 696: 64 blocks, kes per b
#define ROLE_BASK_BASE (ROLE_KES_BASE+BB)  // 760
#define NBLK_BASK      (BB*10)             // 640: (b, t-pair), 8 warps
#define NTOT           (ROLE_BASK_BASE+NBLK_BASK)  // 1400

// ---------------- scratch (no allocations allowed) ----------------
__device__ float g_A[BB*KK*KK];     // A[b,k,j] = alpha_c[k] . rho_c[j]
__device__ float g_rda0[BB*TT*KK];  // rho_c[j] . alpha_item0[t]
__device__ float g_P[BB*TT*KK];     // rho_item0[t] . alpha_c[k]
__device__ float g_ra00[BB*TT];     // rho_item0 . alpha_item0
__device__ float g_kesc[BB*KK];
__device__ float g_kes0[BB*TT];
__device__ float g_part_rows[NBLK_ROWS];
__device__ float g_part_bask[NBLK_BASK];
__device__ unsigned g_ready[BB];    // per-b producer count (4 expected); reset by last block
__device__ unsigned g_count;        // completion ticket; reset by last block

// order-preserving float<->int map (self-inverse)
__device__ __forceinline__ int f_ord(float f) {
    int i = __float_as_int(f);
    return i ^ ((i >> 31) & 0x7FFFFFFF);
}
__device__ __forceinline__ float ord_f(int i) {
    i ^= ((i >> 31) & 0x7FFFFFFF);
    return __int_as_float(i);
}

// =====================================================================
// One fused kernel. Producers (rows/A/rda0/P/kes) occupy low block ids;
// basket consumers spin on per-b flags. Last-ticket block reduces.
// =====================================================================
__global__ void __launch_bounds__(256) fused_kernel(
    const float* __restrict__ alpha, const float* __restrict__ rho,
    const float* __restrict__ lam,   const float* __restrict__ beta,
    const float* __restrict__ mu_tab,const float* __restrict__ theta,
    const float* __restrict__ gamma,
    const float* __restrict__ w1, const float* __restrict__ b1,
    const float* __restrict__ w2, const float* __restrict__ b2,
    const float* __restrict__ sigma, const float* __restrict__ mu,
    const float* __restrict__ prices, const float* __restrict__ price_table,
    const int* __restrict__ item_ids, const int* __restrict__ itemset,
    const int* __restrict__ userid, float* __restrict__ out)
{
    __shared__ __align__(16) char smem_raw[43008];
    __shared__ float ws[8];
    __shared__ double wd[8];
    __shared__ int is_last;
    const unsigned FULL = 0xffffffffu;
    int bx = blockIdx.x, tid = threadIdx.x;

    if (bx < NBLK_ROWS) {
        // ============ rows role: Qf + prior over 32 gathered rows ============
        float* w1t   = (float*)smem_raw;        // [e][h] pitch 68
        float* v_rm  = w1t + EE*68;             // [row][e]
        float* ssrow = v_rm + RROWS*EE;
        float* w2s   = ssrow + RROWS;
        float* b1s   = w2s + HH;
        float* bsum  = b1s + HH;

        int base = bx * RROWS;
        int g; const float* tab; int uoff = 0;
        if (base < 5*BB*KK) {
            g = base / (BB*KK);
            tab = (g==0)?alpha : (g==1)?rho : (g==2)?lam : (g==3)?beta : mu_tab;
        } else if (base < 5*BB*KK + BB) { g = 5; tab = theta; uoff = base - 5*BB*KK; }
        else                            { g = 6; tab = gamma; uoff = base - 5*BB*KK - BB; }
        float sg = sigma[g], muv = mu[g];
        float b2v = b2[0];

        for (int i = tid; i < HH*EE; i += 256) {
            int h = i / EE, e = i - h*EE;
            w1t[e*68 + h] = w1[i];
        }
        if (tid < HH) { w2s[tid] = w2[tid]; b1s[tid] = b1[tid]; }
        if (tid == 0) *bsum = 0.f;

        for (int i = tid; i < RROWS*EE; i += 256) {
            int rl = i / EE, e = i - rl*EE;
            int idx;
            if (g < 5) idx = itemset[base - g*(BB*KK) + rl];
            else       idx = userid[uoff + rl];
            v_rm[rl*EE + e] = tab[(size_t)idx*EE + e];
        }
        __syncthreads();

        if (tid < RROWS) {
            float ss = 0.f;
            for (int e = 0; e < EE; e++) { float x = v_rm[tid*EE + e] - muv; ss = fmaf(x, x, ss); }
            ssrow[tid] = ss;
        }

        int ty = tid >> 4, tx = tid & 15;
        float acc[2][4];
        #pragma unroll
        for (int i = 0; i < 2; i++)
            #pragma unroll
            for (int j = 0; j < 4; j++) acc[i][j] = b1s[tx*4 + j];

        for (int e = 0; e < EE; e++) {
            float4 wv = *(const float4*)&w1t[e*68 + tx*4];
            float vv0 = v_rm[(2*ty + 0)*EE + e];
            float vv1 = v_rm[(2*ty + 1)*EE + e];
            acc[0][0] = fmaf(vv0, wv.x, acc[0][0]);
            acc[0][1] = fmaf(vv0, wv.y, acc[0][1]);
            acc[0][2] = fmaf(vv0, wv.z, acc[0][2]);
            acc[0][3] = fmaf(vv0, wv.w, acc[0][3]);
            acc[1][0] = fmaf(vv1, wv.x, acc[1][0]);
            acc[1][1] = fmaf(vv1, wv.y, acc[1][1]);
            acc[1][2] = fmaf(vv1, wv.z, acc[1][2]);
            acc[1][3] = fmaf(vv1, wv.w, acc[1][3]);
        }

        float z[2];
        #pragma unroll
        for (int i = 0; i < 2; i++) {
            float s = 0.f;
            #pragma unroll
            for (int j = 0; j < 4; j++) s = fmaf(fmaxf(acc[i][j], 0.f), w2s[tx*4 + j], s);
            z[i] = s;
        }
        #pragma unroll
        for (int o = 8; o; o >>= 1) {
            z[0] += __shfl_xor_sync(FULL, z[0], o);
            z[1] += __shfl_xor_sync(FULL, z[1], o);
        }
        __syncthreads();
        if (tx == 0) {
            float local = 0.f;
            #pragma unroll
            for (int i = 0; i < 2; i++) {
                float q = 1.f / (1.f + expf(-(z[i] + b2v)));
                local += (-0.5f/sg)*ssrow[2*ty + i] - q;
            }
            atomicAdd(bsum, local);
        }
        __syncthreads();
        if (tid == 0) g_part_rows[bx] = *bsum;

    } else if (bx < ROLE_RDA0_BASE) {
        // ============ A[b,k,j] Gram, 4x4 tiles ============
        int b = bx - ROLE_A_BASE;
        float* sA = (float*)smem_raw;      // [e][k] pitch 52
        float* sR = sA + EE*52;
        for (int i = tid; i < 2*EE; i += 256) { int e = i >> 1, k = 50 + (i & 1); sA[e*52+k]=0.f; sR[e*52+k]=0.f; }
        for (int i = tid; i < KK*EE; i += 256) {
            int k = i / EE, e = i - k*EE; int row = itemset[b*KK + k];
            sA[e*52 + k] = alpha[(size_t)row*EE + e];
            sR[e*52 + k] = rho  [(size_t)row*EE + e];
        }
        __syncthreads();
        if (tid < 169) {
            int ty = tid / 13, tx = tid - ty*13;
            float acc[4][4] = {};
            for (int e = 0; e < EE; e++) {
                float4 av = *(const float4*)&sA[e*52 + ty*4];
                float4 rv = *(const float4*)&sR[e*52 + tx*4];
                float aa[4] = {av.x, av.y, av.z, av.w};
                float rr[4] = {rv.x, rv.y, rv.z, rv.w};
                #pragma unroll
                for (int i = 0; i < 4; i++)
                    #pragma unroll
                    for (int j = 0; j < 4; j++) acc[i][j] = fmaf(aa[i], rr[j], acc[i][j]);
            }
            #pragma unroll
            for (int i = 0; i < 4; i++) {
                int k = ty*4 + i; if (k >= KK) break;
                #pragma unroll
                for (int j = 0; j < 4; j++) {
                    int jj = tx*4 + j;
                    if (jj < KK) g_A[(b*KK + k)*KK + jj] = acc[i][j];
                }
            }
        }
        __syncthreads();
        if (tid == 0) { __threadfence(); atomicAdd(&g_ready[b], 1u); }

    } else if (bx < ROLE_P_BASE) {
        // ============ rda0[b,t,j] = alpha_item0[t] . rho_c[j] ============
        int b = bx - ROLE_RDA0_BASE;
        float* sR  = (float*)smem_raw;     // [e][j] pitch 52
        float* sA0 = sR + EE*52;           // [e][t] pitch 20
        for (int i = tid; i < 2*EE; i += 256) { int e = i >> 1, k = 50 + (i & 1); sR[e*52+k]=0.f; }
        for (int i = tid; i < KK*EE; i += 256) {
            int k = i / EE, e = i - k*EE; int row = itemset[b*KK + k];
            sR[e*52 + k] = rho[(size_t)row*EE + e];
        }
        for (int i = tid; i < TT*EE; i += 256) {
            int t = i / EE, e = i - t*EE; int row = item_ids[b*TT + t];
            sA0[e*20 + t] = alpha[(size_t)row*EE + e];
        }
        __syncthreads();
        if (tid < 65) {
            int ty = tid / 13, tx = tid - ty*13;
            float acc[4][4] = {};
            for (int e = 0; e < EE; e++) {
                float4 av = *(const float4*)&sA0[e*20 + ty*4];
                float4 rv = *(const float4*)&sR[e*52 + tx*4];
                float aa[4] = {av.x, av.y, av.z, av.w};
                float rr[4] = {rv.x, rv.y, rv.z, rv.w};
                #pragma unroll
                for (int i = 0; i < 4; i++)
                    #pragma unroll
                    for (int j = 0; j < 4; j++) acc[i][j] = fmaf(aa[i], rr[j], acc[i][j]);
            }
            #pragma unroll
            for (int i = 0; i < 4; i++) {
                int t = ty*4 + i;
                #pragma unroll
                for (int j = 0; j < 4; j++) {
                    int jj = tx*4 + j;
                    if (jj < KK) g_rda0[(b*TT + t)*KK + jj] = acc[i][j];
                }
            }
        }
        __syncthreads();
        if (tid == 0) { __threadfence(); atomicAdd(&g_ready[b], 1u); }

    } else if (bx < ROLE_KES_BASE) {
        // ============ P[b,t,k] = rho_item0[t] . alpha_c[k]; ra00 ============
        int b = bx - ROLE_P_BASE;
        float* sAC = (float*)smem_raw;     // [e][k] pitch 52
        float* sR0 = sAC + EE*52;          // [e][t] pitch 20
        float* sA0 = sR0 + EE*20;
        for (int i = tid; i < 2*EE; i += 256) { int e = i >> 1, k = 50 + (i & 1); sAC[e*52+k]=0.f; }
        for (int i = tid; i < KK*EE; i += 256) {
            int k = i / EE, e = i - k*EE; int row = itemset[b*KK + k];
            sAC[e*52 + k] = alpha[(size_t)row*EE + e];
        }
        for (int i = tid; i < TT*EE; i += 256) {
            int t = i / EE, e = i - t*EE; int row = item_ids[b*TT + t];
            sR0[e*20 + t] = rho  [(size_t)row*EE + e];
            sA0[e*20 + t] = alpha[(size_t)row*EE + e];
        }
        __syncthreads();
        if (tid < 65) {
            int ty = tid / 13, tx = tid - ty*13;
            float acc[4][4] = {};
            for (int e = 0; e < EE; e++) {
                float4 rv = *(const float4*)&sR0[e*20 + ty*4];
                float4 av = *(const float4*)&sAC[e*52 + tx*4];
                float rr[4] = {rv.x, rv.y, rv.z, rv.w};
                float aa[4] = {av.x, av.y, av.z, av.w};
                #pragma unroll
                for (int i = 0; i < 4; i++)
                    #pragma unroll
                    for (int j = 0; j < 4; j++) acc[i][j] = fmaf(rr[i], aa[j], acc[i][j]);
            }
            #pragma unroll
            for (int i = 0; i < 4; i++) {
                int t = ty*4 + i;
                #pragma unroll
                for (int j = 0; j < 4; j++) {
                    int kk = tx*4 + j;
                    if (kk < KK) g_P[(b*TT + t)*KK + kk] = acc[i][j];
                }
            }
        }
        if (tid >= 96 && tid < 96 + TT) {
            int t = tid - 96;
            float s = 0.f;
            for (int e = 0; e < EE; e++) s = fmaf(sR0[e*20 + t], sA0[e*20 + t], s);
            g_ra00[b*TT + t] = s;
        }
        __syncthreads();
        if (tid == 0) { __threadfence(); atomicAdd(&g_ready[b], 1u); }

    } else if (bx < ROLE_BASK_BASE) {
        // ============ kes role, one block per b (70 entries, 8 warps) ============
        int b = bx - ROLE_KES_BASE;
        int w = tid >> 5, lane = tid & 31;
        int u = userid[b];
        const float* th = theta + (size_t)u*EE;
        const float* ga = gamma + (size_t)u*EE;
        float th0 = th[lane], th1 = th[32+lane], th2 = th[64+lane];
        float ga0 = ga[lane], ga1 = ga[32+lane], ga2 = ga[64+lane];
        float th3 = (lane < 4) ? th[96+lane] : 0.f;
        float ga3 = (lane < 4) ? ga[96+lane] : 0.f;

        for (int e = w; e < KK + TT; e += 8) {
            int idx; float price; bool is_c = (e < KK);
            if (is_c) { idx = itemset[b*KK + e]; price = price_table[idx]; }
            else      { int t = e - KK; idx = item_ids[b*TT + t]; price = prices[b*TT + t]; }
            const float* a  = alpha + (size_t)idx*EE;
            const float* l  = lam   + (size_t)idx*EE;
            const float* be = beta  + (size_t)idx*EE;
            float a0 = a[lane], a1 = a[32+lane], a2 = a[64+lane];
            float l0 = l[lane], l1 = l[32+lane], l2 = l[64+lane];
            float be0 = be[lane], be1 = be[32+lane], be2 = be[64+lane];
            float a3 = 0.f, l3 = 0.f, be3 = 0.f;
            if (lane < 4) { a3 = a[96+lane]; l3 = l[96+lane]; be3 = be[96+lane]; }

            float s1 = l0 + l1 + l2 + l3;
            float s2 = fmaf(th0,a0, fmaf(th1,a1, fmaf(th2,a2, th3*a3)));
            float s3 = fmaf(ga0,be0, fmaf(ga1,be1, fmaf(ga2,be2, ga3*be3)));
            #pragma unroll
            for (int o = 16; o; o >>= 1) {
                s1 += __shfl_xor_sync(FULL, s1, o);
                s2 += __shfl_xor_sync(FULL, s2, o);
                s3 += __shfl_xor_sync(FULL, s3, o);
            }
            if (lane == 0) {
                float val = (s1 + s2) * (1.f/EE) - (s3 * (1.f/EE)) * logf(price);
                if (is_c) g_kesc[b*KK + e] = val; else g_kes0[b*TT + (e - KK)] = val;
            }
        }
        __syncthreads();
        if (tid == 0) { __threadfence(); atomicAdd(&g_ready[b], 1u); }

    } else {
        // ============ basket role: 2 t's x 4 k-chunks per block ============
        int bx2 = bx - ROLE_BASK_BASE;      // 0..639
        int b = bx2 / 10, pair = bx2 % 10;
        int w = tid >> 5, lane = tid & 31;
        int sub = w >> 2, chunk = w & 3;
        int t = pair*2 + sub;
        int bt = b*TT + t;
        int base = b*KK;
        int kstart = (chunk*KK) >> 2;       // 0,12,25,37
        int kend   = ((chunk+1)*KK) >> 2;   // 12,25,37,50

        // inputs not produced in-kernel can be read pre-wait
        int item0 = item_ids[bt];
        bool v1 = (lane < KK - 32);
        int c0i = itemset[base + lane];
        int c1i = v1 ? itemset[base + 32 + lane] : 0;
        bool mj0 = (c0i != item0);
        bool mj1 = v1 && (c1i != item0);
        unsigned ball0 = __ballot_sync(FULL, mj0);
        unsigned ball1 = __ballot_sync(FULL, mj1);
        int popA = __popc(ball0);

        // wait for this b's producers (A, rda0, P, kes)
        if (tid == 0) {
            volatile unsigned* f = &g_ready[b];
            while (*f < 4u) __nanosleep(64);
        }
        __syncthreads();
        __threadfence();

        float* sA = (float*)smem_raw;       // A[b] [k][j], 10KB
        for (int i = tid; i < KK*KK; i += 256) sA[i] = g_A[base*KK + i];

        float kesc0 = g_kesc[base + lane];
        float kesc1 = v1 ? g_kesc[base + 32 + lane] : 0.f;
        float rj0 = g_rda0[bt*KK + lane];
        float rj1 = v1 ? g_rda0[bt*KK + 32 + lane] : 0.f;
        float ra00  = g_ra00[bt];
        float kes0v = g_kes0[bt];

        // one-time masked inclusive prefix scan of P over k (two 32-halves)
        float px0 = mj0 ? g_P[bt*KK + lane] : 0.f;
        float px1 = mj1 ? g_P[bt*KK + 32 + lane] : 0.f;
        #pragma unroll
        for (int d = 1; d < 32; d <<= 1) {
            float v = __shfl_up_sync(FULL, px0, d);
            if (lane >= d) px0 += v;
        }
        float tot0 = __shfl_sync(FULL, px0, 31);
        #pragma unroll
        for (int d = 1; d < 32; d <<= 1) {
            float v = __shfl_up_sync(FULL, px1, d);
            if (lane >= d) px1 += v;
        }
        px1 += tot0;

        __syncthreads();   // sA ready

        // chunk base: Cj up to kstart (cheap pipelined masked FMAs)
        float Cj0 = 0.f, Cj1 = 0.f, acc = 0.f;
        for (int k = 0; k < kstart; k++) {
            float mf = ((k < 32 ? (ball0 >> k) : (ball1 >> (k-32))) & 1u) ? 1.f : 0.f;
            Cj0 = fmaf(mf, sA[k*KK + lane], Cj0);
            if (v1) Cj1 = fmaf(mf, sA[k*KK + 32 + lane], Cj1);
        }
        // running count of set bits strictly below kstart
        int cnt;
        if (kstart == 0)        cnt = 0;
        else if (kstart <= 32)  cnt = __popc(ball0 & ((1u << kstart) - 1u));
        else                    cnt = popA + __popc(ball1 & ((1u << (kstart-32)) - 1u));

        for (int k = kstart; k < kend; k++) {
            bool mk = ((k < 32 ? (ball0 >> k) : (ball1 >> (k-32))) & 1u);
            if (mk) {   // uniform branch; when item0 == c_k the step is a no-op
                cnt++;
                float ak0 = sA[k*KK + lane];
                float ak1 = v1 ? sA[k*KK + 32 + lane] : 0.f;
                Cj0 += ak0;
                Cj1 += ak1;

                float lenk   = 1.f + (float)cnt;
                float rdenom = __fdividef(1.f, (lenk + 1.f) * (float)EE);

                float c0 = -INFINITY, cc = -INFINITY;
                if (mj0 && lane > k) {
                    float bs = rj0 + Cj0;
                    c0 = fmaf(bs + rj0, rdenom, kesc0);
                    cc = fmaf(bs + ak0, rdenom, kesc0);
                }
                if (mj1 && (lane + 32) > k) {
                    float bs = rj1 + Cj1;
                    float y0 = fmaf(bs + rj1, rdenom, kesc1);
                    float yc = fmaf(bs + ak1, rdenom, kesc1);
                    c0 = fmaxf(c0, y0); cc = fmaxf(cc, yc);
                }

                int m0i = __reduce_max_sync(FULL, f_ord(c0));
                int mci = __reduce_max_sync(FULL, f_ord(cc));

                if (lane == (k & 31)) {     // designated j==k; mjd == mk == true here
                    float m0 = ord_f(m0i);
                    float mc = ord_f(mci);
                    float kescd = (k < 32) ? kesc0 : kesc1;
                    float rjd   = (k < 32) ? rj0   : rj1;
                    float Cjd   = (k < 32) ? Cj0   : Cj1;
                    float Pcd   = (k < 32) ? px0   : px1;
                    float inv = __fdividef(1.f, (float)EE * lenk);
                    float i0v = (ra00 + Pcd) * inv;
                    float icv = (rjd  + Cjd) * inv;
                    float Kes0 = kes0v + i0v + fmaxf(0.f, m0);
                    float KesC = kescd + icv + fmaxf(0.f, mc);
                    float xq = Kes0 - KesC;
                    acc += fminf(xq, 0.f) - log1pf(expf(-fabsf(xq)));
                }
            }
        }

        #pragma unroll
        for (int o = 16; o; o >>= 1) acc += __shfl_xor_sync(FULL, acc, o);
        if (lane == 0) ws[w] = acc;
        __syncthreads();
        if (tid == 0) {
            float s = 0.f;
            #pragma unroll
            for (int i = 0; i < 8; i++) s += ws[i];
            g_part_bask[bx2] = s;
        }
    }

    // ================= common epilogue: completion ticket =================
    __syncthreads();
    if (tid == 0) {
        __threadfence();
        unsigned tk = atomicAdd(&g_count, 1u);
        is_last = (tk == NTOT - 1) ? 1 : 0;
    }
    __syncthreads();

    if (is_last) {
        __threadfence();  // see all blocks' partial stores
        double s = 0.0;
        for (int i = tid; i < NBLK_ROWS; i += 256) s += (double)g_part_rows[i];
        for (int i = tid; i < NBLK_BASK; i += 256) s += (double)g_part_bask[i];
        #pragma unroll
        for (int o = 16; o; o >>= 1) s += __shfl_xor_sync(FULL, s, o);
        if ((tid & 31) == 0) wd[tid >> 5] = s;
        __syncthreads();
        if (tid == 0) {
            double tt = 0.0;
            #pragma unroll
            for (int i = 0; i < 8; i++) tt += wd[i];
            out[0] = (float)tt;
            g_count = 0u;                       // reset for next replay
        }
        if (tid < BB) g_ready[tid] = 0u;        // reset flags for next replay
    }
}

// ================= launch: ONE node, no driver objects ================
extern "C" void kernel_launch(void* const* d_in, const int* in_sizes, int n_in,
                              void* d_out, int out_size)
{
    const float* alpha       = (const float*)d_in[0];
    const float* rho         = (const float*)d_in[1];
    const float* lam         = (const float*)d_in[2];
    const float* beta        = (const float*)d_in[3];
    const float* mu_tab      = (const float*)d_in[4];
    const float* theta       = (const float*)d_in[5];
    const float* gamma       = (const float*)d_in[6];
    const float* w1          = (const float*)d_in[7];
    const float* b1          = (const float*)d_in[8];
    const float* w2          = (const float*)d_in[9];
    const float* b2          = (const float*)d_in[10];
    const float* sigma_list  = (const float*)d_in[11];
    const float* mu_list     = (const float*)d_in[12];
    const float* prices      = (const float*)d_in[13];
    const float* price_table = (const float*)d_in[14];
    const int*   item_ids    = (const int*)d_in[15];
    const int*   itemset     = (const int*)d_in[16];
    const int*   userid      = (const int*)d_in[17];

    fused_kernel<<<NTOT, 256>>>(alpha, rho, lam, beta, mu_tab, theta, gamma,
                                w1, b1, w2, b2, sigma_list, mu_list,
                                prices, price_table, item_ids, itemset, userid,
                                (float*)d_out);
}